// round 13
// baseline (speedup 1.0000x reference)
#include <cuda_runtime.h>
#include <cuda_bf16.h>
#include <cstdint>

#define DD   128
#define NN   21845          // (4^8 - 1) / 3
#define NPOS 18
#define NDEP 46
#define NMAT (NPOS + NDEP)

__host__ __device__ __forceinline__ int lvl_start(int l) {
    return ((1 << (2 * l)) - 1) / 3;
}

typedef unsigned long long ull;

__device__ __forceinline__ void fma2(ull& acc, ull a, ull b) {
    asm("fma.rn.f32x2 %0, %1, %2, %0;" : "+l"(acc) : "l"(a), "l"(b));
}
__device__ __forceinline__ void unpack2(ull v, float& lo, float& hi) {
    asm("mov.b64 {%0, %1}, %2;" : "=f"(lo), "=f"(hi) : "l"(v));
}
__device__ __forceinline__ float4 max4(float4 a, float4 b) {
    float4 r;
    r.x = fmaxf(a.x, b.x); r.y = fmaxf(a.y, b.y);
    r.z = fmaxf(a.z, b.z); r.w = fmaxf(a.w, b.w);
    return r;
}
__device__ __forceinline__ unsigned sw16(unsigned b) {
    return b ^ ((b >> 3) & 0x10u);
}
__device__ __forceinline__ uint32_t smem_u32(const void* p) {
    uint32_t a;
    asm("{ .reg .u64 t; cvta.to.shared.u64 t, %1; cvt.u32.u64 %0, t; }"
        : "=r"(a) : "l"(p));
    return a;
}
__device__ __forceinline__ void cpasync16(uint32_t dst, const void* src) {
    asm volatile("cp.async.cg.shared.global [%0], [%1], 16;"
                 :: "r"(dst), "l"(src));
}
__device__ __forceinline__ void mma16816(float& d0, float& d1, float& d2, float& d3,
                                         uint32_t a0, uint32_t a1, uint32_t a2,
                                         uint32_t a3, uint32_t b0, uint32_t b1) {
    asm volatile(
        "mma.sync.aligned.m16n8k16.row.col.f32.bf16.bf16.f32 "
        "{%0,%1,%2,%3}, {%4,%5,%6,%7}, {%8,%9}, {%0,%1,%2,%3};"
        : "+f"(d0), "+f"(d1), "+f"(d2), "+f"(d3)
        : "r"(a0), "r"(a1), "r"(a2), "r"(a3), "r"(b0), "r"(b1));
}

// ---------------- persistent scratch ----------------
__device__ float g_xz[NN * DD];
__device__ float g_u[NN * DD];
__device__ __nv_bfloat16 g_wsp[(size_t)NMAT * 32768];  // WT hi then lo per matrix
__device__ int   g_pos_perm[NN];
__device__ int   g_pos_off[NPOS + 1];
__device__ int   g_pos_tg[384], g_pos_tb[384];
__device__ int   g_pos_nt;
__device__ int   g_dep_perm[NN];
__device__ int   g_dep_off[7][NDEP + 1];
__device__ int   g_dep_tg[7][320], g_dep_tb[7][320];
__device__ int   g_dep_nt[7];
__device__ unsigned g_bar_cnt;
__device__ unsigned g_bar_gen;    // monotonic -> graph-replay safe

__device__ __forceinline__ void gridbar(int nb) {
    __syncthreads();
    if (threadIdx.x == 0) {
        __threadfence();
        unsigned gen = *(volatile unsigned*)&g_bar_gen;
        if (atomicAdd(&g_bar_cnt, 1u) == (unsigned)nb - 1u) {
            atomicExch(&g_bar_cnt, 0u);
            __threadfence();
            atomicAdd(&g_bar_gen, 1u);
        } else {
            while (*(volatile unsigned*)&g_bar_gen == gen) __nanosleep(64);
        }
        __threadfence();
    }
    __syncthreads();
}

// ---- smem layout (dynamic, 105472 B -> 2 CTAs/SM) ----
#define TSTR 68
#define TROW 272
#define OFF_AH 1024
#define OFF_AL (OFF_AH + 64 * TROW)
#define OFF_WH (OFF_AL + 64 * TROW)
#define OFF_WL (OFF_WH + 128 * TROW)
#define SMEM_T (OFF_WL + 128 * TROW)   // 105472

// ---------------------------------------------------------------------------
__device__ __noinline__ void do_group(char* smem, const int* pos_ids,
                                      const int* dep_ids, int b) {
    int* cnt = (int*)smem;
    int* off = (int*)(smem + 256);
    int t = threadIdx.x, lane = t & 31;
    const int* ids; int n, ng, base, BM;
    int *perm, *goff, *tg, *tb, *nt_out;
    if (b == 0) {
        ids = pos_ids; n = NN; ng = NPOS; base = 0; BM = 64;
        perm = g_pos_perm; goff = g_pos_off;
        tg = g_pos_tg; tb = g_pos_tb; nt_out = &g_pos_nt;
    } else {
        int l = b - 1;
        base = lvl_start(l + 1); n = 1 << (2 * (l + 1)); ng = NDEP;
        BM = (l >= 4) ? 64 : 16;
        ids = dep_ids + base; perm = g_dep_perm + base; goff = g_dep_off[l];
        tg = g_dep_tg[l]; tb = g_dep_tb[l]; nt_out = &g_dep_nt[l];
    }
    if (t < ng) cnt[t] = 0;
    __syncthreads();
    for (int i0 = 0; i0 < n; i0 += 256) {
        int i = i0 + t; bool v = (i < n);
        unsigned act = __ballot_sync(0xffffffffu, v);
        if (v) {
            int id = ids[i];
            unsigned m = __match_any_sync(act, id);
            if (lane == __ffs(m) - 1) atomicAdd(&cnt[id], __popc(m));
        }
    }
    __syncthreads();
    if (t == 0) {
        int s = 0;
        for (int j = 0; j < ng; ++j) { off[j] = s; s += cnt[j]; }
        off[ng] = s;
        int nt = 0;
        for (int j = 0; j < ng; ++j) {
            int c = off[j + 1] - off[j];
            for (int k = 0; k < c; k += BM) { tg[nt] = j; tb[nt] = off[j] + k; ++nt; }
        }
        *nt_out = nt;
        for (int j = 0; j <= ng; ++j) goff[j] = off[j];
    }
    __syncthreads();
    if (t < ng) cnt[t] = off[t];
    __syncthreads();
    for (int i0 = 0; i0 < n; i0 += 256) {
        int i = i0 + t; bool v = (i < n);
        unsigned act = __ballot_sync(0xffffffffu, v);
        if (v) {
            int id = ids[i];
            unsigned m = __match_any_sync(act, id);
            int leader = __ffs(m) - 1;
            int prior = __popc(m & ((1u << lane) - 1u));
            int bp = 0;
            if (lane == leader) bp = atomicAdd(&cnt[id], __popc(m));
            bp = __shfl_sync(act, bp, leader);
            perm[bp + prior] = base + i;
        }
    }
}

__device__ __noinline__ void do_presplit(char* smem, int j,
                                         const float* pos_W, const float* dep_W) {
    float* sw = (float*)(smem + 1024);   // 64 x 132 floats
    int t = threadIdx.x;
    const float* Wsrc = (j < NPOS) ? pos_W + (size_t)j * 16384
                                   : dep_W + (size_t)(j - NPOS) * 16384;
    uint32_t* hi = (uint32_t*)(g_wsp + (size_t)j * 32768);
    uint32_t* lo = (uint32_t*)(g_wsp + (size_t)j * 32768 + 16384);
    for (int r = 0; r < 2; ++r) {
        __syncthreads();
        for (int idx = t; idx < 64 * 128; idx += 256) {
            int d = idx >> 7, e2 = idx & 127;
            sw[d * 132 + e2] = Wsrc[(r * 64 + d) * 128 + e2];
        }
        __syncthreads();
        int e = t & 127, half = t >> 7;
#pragma unroll 4
        for (int d0 = half * 32; d0 < half * 32 + 32; d0 += 2) {
            float x0 = sw[d0 * 132 + e];
            float x1 = sw[(d0 + 1) * 132 + e];
            __nv_bfloat16 h0 = __float2bfloat16(x0);
            __nv_bfloat16 h1 = __float2bfloat16(x1);
            __nv_bfloat162 hp; hp.x = h0; hp.y = h1;
            __nv_bfloat162 lp;
            lp.x = __float2bfloat16(x0 - __bfloat162float(h0));
            lp.y = __float2bfloat16(x1 - __bfloat162float(h1));
            int u32idx = (e * 128 + r * 64 + d0) >> 1;
            hi[u32idx] = *(uint32_t*)&hp;
            lo[u32idx] = *(uint32_t*)&lp;
        }
    }
}

// ---------------------------------------------------------------------------
// HMMA tile: BM=64 x 128 x K=128, bf16 split 3-pass, 256 thr / 8 warps.
// mode 0: A=emb -> g_xz; mode 1: A=g_xz -> g_u; mode 2: A=max(x,u-kids) -> g_u
// ---------------------------------------------------------------------------
__device__ __forceinline__ void hmma_tile(
    char* smem, int mode, int j, int b0, const int* off, int woff,
    const float* bias, const float* srcA, const int* perm,
    int cs_row, int cs_child)
{
    int t = threadIdx.x;
    int*   sNode = (int*)smem;
    float* sBias = (float*)(smem + 512);
    uint32_t sbase = smem_u32(smem);
    int mc = off[j + 1] - b0; if (mc > 64) mc = 64;
    __syncthreads();   // protect smem reuse across tiles/phases
    if (t < 64)  sNode[t] = perm[b0 + min(t, mc - 1)];
    if (t < 128) sBias[t] = bias[j * 128 + t];
    __syncthreads();

    // W staging via cp.async
    {
        const uint4* srcH = (const uint4*)(g_wsp + (size_t)(woff + j) * 32768);
        const uint4* srcL = srcH + 2048;
#pragma unroll
        for (int i = 0; i < 8; ++i) {
            int idx = t + 256 * i;
            int r = idx >> 4, c = idx & 15;
            cpasync16(sbase + OFF_WH + r * TROW + 16 * c, srcH + idx);
            cpasync16(sbase + OFF_WL + r * TROW + 16 * c, srcL + idx);
        }
        asm volatile("cp.async.commit_group;");
    }
    // A staging: gather (+max over kids), split hi/lo
    {
        const float4* X4 = (const float4*)srcA;
        const float4* U4 = (const float4*)g_u;
#pragma unroll
        for (int i = 0; i < 8; ++i) {
            int idx = t + 256 * i;
            int r = idx >> 5, c = idx & 31;
            int node = sNode[r];
            float4 v = X4[(size_t)node * 32 + c];
            if (mode == 2) {
                int ch = cs_child + 4 * (node - cs_row);
                v = max4(v, U4[(size_t)(ch + 0) * 32 + c]);
                v = max4(v, U4[(size_t)(ch + 1) * 32 + c]);
                v = max4(v, U4[(size_t)(ch + 2) * 32 + c]);
                v = max4(v, U4[(size_t)(ch + 3) * 32 + c]);
            }
            __nv_bfloat16 h0 = __float2bfloat16(v.x), h1 = __float2bfloat16(v.y);
            __nv_bfloat16 h2 = __float2bfloat16(v.z), h3 = __float2bfloat16(v.w);
            __nv_bfloat162 ha; ha.x = h0; ha.y = h1;
            __nv_bfloat162 hb; hb.x = h2; hb.y = h3;
            __nv_bfloat162 la, lb;
            la.x = __float2bfloat16(v.x - __bfloat162float(h0));
            la.y = __float2bfloat16(v.y - __bfloat162float(h1));
            lb.x = __float2bfloat16(v.z - __bfloat162float(h2));
            lb.y = __float2bfloat16(v.w - __bfloat162float(h3));
            uint2 hh; hh.x = *(uint32_t*)&ha; hh.y = *(uint32_t*)&hb;
            uint2 ll; ll.x = *(uint32_t*)&la; ll.y = *(uint32_t*)&lb;
            *(uint2*)(smem + OFF_AH + r * TROW + 8 * c) = hh;
            *(uint2*)(smem + OFF_AL + r * TROW + 8 * c) = ll;
        }
    }
    asm volatile("cp.async.wait_group 0;" ::: "memory");
    __syncthreads();

    int lane = t & 31, warp = t >> 5;
    int g = lane >> 2, tid = lane & 3;
    int m0 = (warp & 1) * 32, n0 = (warp >> 1) * 32;

    float acc[2][4][4];
#pragma unroll
    for (int mt = 0; mt < 2; ++mt)
#pragma unroll
        for (int nt = 0; nt < 4; ++nt)
#pragma unroll
            for (int q = 0; q < 4; ++q) acc[mt][nt][q] = 0.f;

    const uint32_t* Ah = (const uint32_t*)(smem + OFF_AH);
    const uint32_t* Al = (const uint32_t*)(smem + OFF_AL);
    const uint32_t* Wh = (const uint32_t*)(smem + OFF_WH);
    const uint32_t* Wl = (const uint32_t*)(smem + OFF_WL);

#pragma unroll
    for (int pass = 0; pass < 3; ++pass) {
        const uint32_t* As = (pass == 2) ? Al : Ah;
        const uint32_t* Ws = (pass == 1) ? Wl : Wh;
#pragma unroll
        for (int k16 = 0; k16 < 8; ++k16) {
            int kb = k16 * 8;
            uint32_t a[2][4];
#pragma unroll
            for (int mt = 0; mt < 2; ++mt) {
                int r = m0 + 16 * mt;
                a[mt][0] = As[(r + g) * TSTR + kb + tid];
                a[mt][1] = As[(r + g + 8) * TSTR + kb + tid];
                a[mt][2] = As[(r + g) * TSTR + kb + tid + 4];
                a[mt][3] = As[(r + g + 8) * TSTR + kb + tid + 4];
            }
#pragma unroll
            for (int nt = 0; nt < 4; ++nt) {
                int e = n0 + 8 * nt + g;
                uint32_t bb0 = Ws[e * TSTR + kb + tid];
                uint32_t bb1 = Ws[e * TSTR + kb + tid + 4];
                mma16816(acc[0][nt][0], acc[0][nt][1], acc[0][nt][2], acc[0][nt][3],
                         a[0][0], a[0][1], a[0][2], a[0][3], bb0, bb1);
                mma16816(acc[1][nt][0], acc[1][nt][1], acc[1][nt][2], acc[1][nt][3],
                         a[1][0], a[1][1], a[1][2], a[1][3], bb0, bb1);
            }
        }
    }

    float* base = (mode == 0) ? g_xz : g_u;
#pragma unroll
    for (int mt = 0; mt < 2; ++mt) {
        int row = m0 + 16 * mt + g;
        int nodeA = sNode[row];
        int nodeB = sNode[row + 8];
#pragma unroll
        for (int nt = 0; nt < 4; ++nt) {
            int c0 = n0 + 8 * nt + 2 * tid;
            float bx = sBias[c0], by = sBias[c0 + 1];
            float2 oA, oB;
            oA.x = fmaxf(acc[mt][nt][0] + bx, 0.f);
            oA.y = fmaxf(acc[mt][nt][1] + by, 0.f);
            oB.x = fmaxf(acc[mt][nt][2] + bx, 0.f);
            oB.y = fmaxf(acc[mt][nt][3] + by, 0.f);
            *(float2*)&base[(size_t)nodeA * 128 + c0] = oA;
            *(float2*)&base[(size_t)nodeB * 128 + c0] = oB;
        }
    }
}

// ---------------------------------------------------------------------------
// Narrow item: 16 rows x 32-col slice, packed-k FFMA2 (levels 3..0).
// ---------------------------------------------------------------------------
__device__ __forceinline__ void narrow_item(
    char* smem, int item, int l, int cs_row, int cs_child,
    const float* Wsrc, const float* bias)
{
    char*  sWn = smem + 1024;                 // 16KB
    float* sA2 = (float*)(smem + 17408);      // 8KB
    int*   sN  = (int*)(smem + 25600);
    int t = threadIdx.x;
    int tile = item >> 2, slice = item & 3, c0 = slice * 32;
    int j = g_dep_tg[l][tile], b0 = g_dep_tb[l][tile];
    int mc = g_dep_off[l][j + 1] - b0; if (mc > 16) mc = 16;
    __syncthreads();
    if (t < 16) sN[t] = g_dep_perm[cs_row + b0 + min(t, mc - 1)];
    const float* Wj = Wsrc + (size_t)j * 16384;
#pragma unroll
    for (int i = 0; i < 2; ++i) {
        int idx = t + 256 * i;
        int kp = idx >> 3, cb = idx & 7;
        float4 r0 = *(const float4*)&Wj[(2 * kp) * 128 + c0 + 4 * cb];
        float4 r1 = *(const float4*)&Wj[(2 * kp + 1) * 128 + c0 + 4 * cb];
        float4 s0 = make_float4(r0.x, r1.x, r0.y, r1.y);
        float4 s1 = make_float4(r0.z, r1.z, r0.w, r1.w);
        unsigned b = (unsigned)(kp * 256 + cb * 32);
        *(float4*)(sWn + sw16(b))      = s0;
        *(float4*)(sWn + sw16(b + 16)) = s1;
    }
    __syncthreads();
    const float4* X4 = (const float4*)g_xz;
    const float4* U4 = (const float4*)g_u;
#pragma unroll
    for (int i = 0; i < 2; ++i) {
        int idx = t + 256 * i; int r = idx >> 5, c = idx & 31;
        int node = sN[r];
        int ch = cs_child + 4 * (node - cs_row);
        float4 v = X4[(size_t)node * 32 + c];
        v = max4(v, U4[(size_t)(ch + 0) * 32 + c]);
        v = max4(v, U4[(size_t)(ch + 1) * 32 + c]);
        v = max4(v, U4[(size_t)(ch + 2) * 32 + c]);
        v = max4(v, U4[(size_t)(ch + 3) * 32 + c]);
        ((float4*)(sA2 + r * 128))[c] = v;
    }
    __syncthreads();
    int r = t >> 4, x16 = t & 15;
    ull accA = 0ull, accB = 0ull;
#pragma unroll 4
    for (int kp = 0; kp < 64; ++kp) {
        ull a = *(const ull*)&sA2[r * 128 + 2 * kp];
        ulonglong2 w = *(const ulonglong2*)(sWn + sw16((unsigned)(kp * 256 + x16 * 16)));
        fma2(accA, a, w.x);
        fma2(accB, a, w.y);
    }
    int node = sN[r];
    int col = c0 + 2 * x16;
    float2 bv = *(const float2*)&bias[j * 128 + col];
    float lo, hi; float2 o;
    unpack2(accA, lo, hi); o.x = fmaxf(lo + hi + bv.x, 0.f);
    unpack2(accB, lo, hi); o.y = fmaxf(lo + hi + bv.y, 0.f);
    *(float2*)&g_u[(size_t)node * 128 + col] = o;
}

// ---------------------------------------------------------------------------
// The persistent mega-kernel
// ---------------------------------------------------------------------------
__global__ __launch_bounds__(256, 2)
void mega_kernel(const float* __restrict__ emb,
                 const int* __restrict__ pos_ids,
                 const int* __restrict__ dep_ids,
                 const float* __restrict__ pos_W, const float* __restrict__ pos_b,
                 const float* __restrict__ dep_W, const float* __restrict__ dep_b,
                 float* __restrict__ out)
{
    extern __shared__ __align__(16) char smem[];
    int nb = gridDim.x, bid = blockIdx.x, t = threadIdx.x;

    // phase 0: grouping (blocks 0..7) + W pre-split (blocks 8..71)
    if (bid < 8) do_group(smem, pos_ids, dep_ids, bid);
    else if (bid < 8 + NMAT) do_presplit(smem, bid - 8, pos_W, dep_W);
    gridbar(nb);

    // phase 1: pos GEMM  (x -> g_xz)
    for (int tile = bid; tile < g_pos_nt; tile += nb)
        hmma_tile(smem, 0, g_pos_tg[tile], g_pos_tb[tile], g_pos_off, 0,
                  pos_b, emb, g_pos_perm, 0, 0);
    gridbar(nb);

    // phase 2: dep level 6 (rows = level-7, z = x) -> g_u
    for (int tile = bid; tile < g_dep_nt[6]; tile += nb)
        hmma_tile(smem, 1, g_dep_tg[6][tile], g_dep_tb[6][tile], g_dep_off[6],
                  NPOS, dep_b, g_xz, g_dep_perm + lvl_start(7), lvl_start(7), 0);
    gridbar(nb);

    // phase 3: dep level 5 (max-gather) -> g_u
    for (int tile = bid; tile < g_dep_nt[5]; tile += nb)
        hmma_tile(smem, 2, g_dep_tg[5][tile], g_dep_tb[5][tile], g_dep_off[5],
                  NPOS, dep_b, g_xz, g_dep_perm + lvl_start(6),
                  lvl_start(6), lvl_start(7));
    gridbar(nb);

    // phase 4: dep level 4 (max-gather) -> g_u
    for (int tile = bid; tile < g_dep_nt[4]; tile += nb)
        hmma_tile(smem, 2, g_dep_tg[4][tile], g_dep_tb[4][tile], g_dep_off[4],
                  NPOS, dep_b, g_xz, g_dep_perm + lvl_start(5),
                  lvl_start(5), lvl_start(6));
    gridbar(nb);

    // phases 5..8: dep levels 3..0 narrow
    for (int l = 3; l >= 0; --l) {
        int cs_row = lvl_start(l + 1);
        int cs_child = lvl_start(l + 2);
        int items = g_dep_nt[l] * 4;
        for (int item = bid; item < items; item += nb)
            narrow_item(smem, item, l, cs_row, cs_child, dep_W, dep_b);
        gridbar(nb);
    }

    // finalize: out = max(x[0], u[1..4])
    if (bid == 0 && t < 32) {
        const float4* X4 = (const float4*)g_xz;
        const float4* U4 = (const float4*)g_u;
        float4 v = X4[t];
        v = max4(v, U4[1 * 32 + t]);
        v = max4(v, U4[2 * 32 + t]);
        v = max4(v, U4[3 * 32 + t]);
        v = max4(v, U4[4 * 32 + t]);
        ((float4*)out)[t] = v;
    }
}

// ---------------------------------------------------------------------------
extern "C" void kernel_launch(void* const* d_in, const int* in_sizes, int n_in,
                              void* d_out, int out_size) {
    const float* emb     = (const float*)d_in[0];
    const int*   pos_ids = (const int*)d_in[1];
    const int*   dep_ids = (const int*)d_in[2];
    const float* pos_W   = (const float*)d_in[3];
    const float* pos_b   = (const float*)d_in[4];
    const float* dep_W   = (const float*)d_in[5];
    const float* dep_b   = (const float*)d_in[6];

    cudaFuncSetAttribute(mega_kernel, cudaFuncAttributeMaxDynamicSharedMemorySize,
                         SMEM_T);
    int dev = 0, nsm = 0, occ = 0;
    cudaGetDevice(&dev);
    cudaDeviceGetAttribute(&nsm, cudaDevAttrMultiProcessorCount, dev);
    cudaOccupancyMaxActiveBlocksPerMultiprocessor(&occ, mega_kernel, 256, SMEM_T);
    if (occ < 1) occ = 1;
    if (occ > 2) occ = 2;
    int grid = nsm * occ;

    mega_kernel<<<grid, 256, SMEM_T>>>(emb, pos_ids, dep_ids,
                                       pos_W, pos_b, dep_W, dep_b,
                                       (float*)d_out);
}

// round 14
// speedup vs baseline: 1.0043x; 1.0043x over previous
#include <cuda_runtime.h>
#include <cuda_bf16.h>
#include <cstdint>

#define DD   128
#define NN   21845          // (4^8 - 1) / 3
#define NPOS 18
#define NDEP 46
#define NMAT (NPOS + NDEP)

__host__ __device__ __forceinline__ int lvl_start(int l) {
    return ((1 << (2 * l)) - 1) / 3;
}

typedef unsigned long long ull;

__device__ __forceinline__ void fma2(ull& acc, ull a, ull b) {
    asm("fma.rn.f32x2 %0, %1, %2, %0;" : "+l"(acc) : "l"(a), "l"(b));
}
__device__ __forceinline__ void unpack2(ull v, float& lo, float& hi) {
    asm("mov.b64 {%0, %1}, %2;" : "=f"(lo), "=f"(hi) : "l"(v));
}
__device__ __forceinline__ float4 max4(float4 a, float4 b) {
    float4 r;
    r.x = fmaxf(a.x, b.x); r.y = fmaxf(a.y, b.y);
    r.z = fmaxf(a.z, b.z); r.w = fmaxf(a.w, b.w);
    return r;
}
__device__ __forceinline__ unsigned sw16(unsigned b) {
    return b ^ ((b >> 3) & 0x10u);
}
__device__ __forceinline__ uint32_t smem_u32(const void* p) {
    uint32_t a;
    asm("{ .reg .u64 t; cvta.to.shared.u64 t, %1; cvt.u32.u64 %0, t; }"
        : "=r"(a) : "l"(p));
    return a;
}
__device__ __forceinline__ void cpasync16(uint32_t dst, const void* src) {
    asm volatile("cp.async.cg.shared.global [%0], [%1], 16;"
                 :: "r"(dst), "l"(src));
}
__device__ __forceinline__ void mma16816(float& d0, float& d1, float& d2, float& d3,
                                         uint32_t a0, uint32_t a1, uint32_t a2,
                                         uint32_t a3, uint32_t b0, uint32_t b1) {
    asm volatile(
        "mma.sync.aligned.m16n8k16.row.col.f32.bf16.bf16.f32 "
        "{%0,%1,%2,%3}, {%4,%5,%6,%7}, {%8,%9}, {%0,%1,%2,%3};"
        : "+f"(d0), "+f"(d1), "+f"(d2), "+f"(d3)
        : "r"(a0), "r"(a1), "r"(a2), "r"(a3), "r"(b0), "r"(b1));
}

// ---------------- persistent scratch ----------------
__device__ float g_xz[NN * DD];
__device__ float g_u[NN * DD];
__device__ __nv_bfloat16 g_wsp[(size_t)NMAT * 32768];  // WT hi then lo per matrix
__device__ int   g_pos_perm[NN];
__device__ int   g_pos_off[NPOS + 1];
__device__ int   g_pos_tg[384], g_pos_tb[384];
__device__ int   g_pos_nt;
__device__ int   g_dep_perm[NN];
__device__ int   g_dep_off[7][NDEP + 1];
__device__ int   g_dep_tg[7][320], g_dep_tb[7][320];
__device__ int   g_dep_nt[7];
__device__ unsigned g_bar_cnt;
__device__ unsigned g_bar_gen;

__device__ __forceinline__ void gridbar(int nb) {
    __syncthreads();
    if (threadIdx.x == 0) {
        __threadfence();
        unsigned gen = *(volatile unsigned*)&g_bar_gen;
        if (atomicAdd(&g_bar_cnt, 1u) == (unsigned)nb - 1u) {
            atomicExch(&g_bar_cnt, 0u);
            __threadfence();
            atomicAdd(&g_bar_gen, 1u);
        } else {
            while (*(volatile unsigned*)&g_bar_gen == gen) __nanosleep(64);
        }
        __threadfence();
    }
    __syncthreads();
}

// ---------------------------------------------------------------------------
// Prep kernel: blocks 0..7 grouping, 8..71 W pre-split (transpose + hi/lo).
// ---------------------------------------------------------------------------
__global__ __launch_bounds__(256)
void prep_kernel(const int* __restrict__ pos_ids, const int* __restrict__ dep_ids,
                 const float* __restrict__ pos_W, const float* __restrict__ dep_W) {
    __shared__ __align__(16) float sw[64 * 132];
    int t = threadIdx.x, lane = t & 31;
    if (blockIdx.x >= 8) {
        int j = blockIdx.x - 8;
        const float* Wsrc = (j < NPOS) ? pos_W + (size_t)j * 16384
                                       : dep_W + (size_t)(j - NPOS) * 16384;
        uint32_t* hi = (uint32_t*)(g_wsp + (size_t)j * 32768);
        uint32_t* lo = (uint32_t*)(g_wsp + (size_t)j * 32768 + 16384);
        for (int r = 0; r < 2; ++r) {
            __syncthreads();
            for (int idx = t; idx < 64 * 128; idx += 256) {
                int d = idx >> 7, e2 = idx & 127;
                sw[d * 132 + e2] = Wsrc[(r * 64 + d) * 128 + e2];
            }
            __syncthreads();
            int e = t & 127, half = t >> 7;
#pragma unroll 4
            for (int d0 = half * 32; d0 < half * 32 + 32; d0 += 2) {
                float x0 = sw[d0 * 132 + e];
                float x1 = sw[(d0 + 1) * 132 + e];
                __nv_bfloat16 h0 = __float2bfloat16(x0);
                __nv_bfloat16 h1 = __float2bfloat16(x1);
                __nv_bfloat162 hp; hp.x = h0; hp.y = h1;
                __nv_bfloat162 lp;
                lp.x = __float2bfloat16(x0 - __bfloat162float(h0));
                lp.y = __float2bfloat16(x1 - __bfloat162float(h1));
                int u32idx = (e * 128 + r * 64 + d0) >> 1;
                hi[u32idx] = *(uint32_t*)&hp;
                lo[u32idx] = *(uint32_t*)&lp;
            }
        }
        return;
    }
    // grouping
    int* cnt = (int*)sw;
    int* off = cnt + NDEP;
    const int* ids; int n, ng, base, BM;
    int *perm, *goff, *tg, *tb, *nt_out;
    if (blockIdx.x == 0) {
        ids = pos_ids; n = NN; ng = NPOS; base = 0; BM = 64;
        perm = g_pos_perm; goff = g_pos_off;
        tg = g_pos_tg; tb = g_pos_tb; nt_out = &g_pos_nt;
    } else {
        int l = blockIdx.x - 1;
        base = lvl_start(l + 1); n = 1 << (2 * (l + 1)); ng = NDEP;
        BM = (l >= 4) ? 64 : 16;
        ids = dep_ids + base; perm = g_dep_perm + base; goff = g_dep_off[l];
        tg = g_dep_tg[l]; tb = g_dep_tb[l]; nt_out = &g_dep_nt[l];
    }
    if (t < ng) cnt[t] = 0;
    __syncthreads();
    for (int i0 = 0; i0 < n; i0 += 256) {
        int i = i0 + t; bool v = (i < n);
        unsigned act = __ballot_sync(0xffffffffu, v);
        if (v) {
            int id = ids[i];
            unsigned m = __match_any_sync(act, id);
            if (lane == __ffs(m) - 1) atomicAdd(&cnt[id], __popc(m));
        }
    }
    __syncthreads();
    if (t == 0) {
        int s = 0;
        for (int j = 0; j < ng; ++j) { off[j] = s; s += cnt[j]; }
        off[ng] = s;
        int nt = 0;
        for (int j = 0; j < ng; ++j) {
            int c = off[j + 1] - off[j];
            for (int k = 0; k < c; k += BM) { tg[nt] = j; tb[nt] = off[j] + k; ++nt; }
        }
        *nt_out = nt;
        for (int j = 0; j <= ng; ++j) goff[j] = off[j];
    }
    __syncthreads();
    if (t < ng) cnt[t] = off[t];
    __syncthreads();
    for (int i0 = 0; i0 < n; i0 += 256) {
        int i = i0 + t; bool v = (i < n);
        unsigned act = __ballot_sync(0xffffffffu, v);
        if (v) {
            int id = ids[i];
            unsigned m = __match_any_sync(act, id);
            int leader = __ffs(m) - 1;
            int prior = __popc(m & ((1u << lane) - 1u));
            int bp = 0;
            if (lane == leader) bp = atomicAdd(&cnt[id], __popc(m));
            bp = __shfl_sync(act, bp, leader);
            perm[bp + prior] = base + i;
        }
    }
}

// ---------------------------------------------------------------------------
// HMMA tile: BM=64 rows x BN=64 cols x K=128, bf16 split 3-pass.
// Block = (tile, colhalf): bid = tile*2 + half, c0 = half*64.
// 256 threads / 8 warps: warp w -> rows (w&1)*32..+31, local cols (w>>1)*16..+15.
// smem 69KB -> 3 CTAs/SM. W via cp.async from pre-split WT; A gather + split.
// mode 0: A=emb -> g_xz; mode 1: A=g_xz -> g_u; mode 2: A=max(x,u-kids) -> g_u
// ---------------------------------------------------------------------------
#define TSTR 68
#define TROW 272
#define OFF_AH 1024
#define OFF_AL (OFF_AH + 64 * TROW)   // 18432
#define OFF_WH (OFF_AL + 64 * TROW)   // 35840
#define OFF_WL (OFF_WH + 64 * TROW)   // 53248
#define SMEM_T (OFF_WL + 64 * TROW)   // 70656 (~69KB) -> 3 CTAs/SM

__global__ __launch_bounds__(256, 3)
void tile_mma(int mode, int woff,
              const float* __restrict__ bias, const float* __restrict__ srcA,
              const int* __restrict__ nt_p, const int* __restrict__ tg,
              const int* __restrict__ tb, const int* __restrict__ off,
              const int* __restrict__ perm, int cs_row, int cs_child)
{
    int tile = blockIdx.x >> 1, half = blockIdx.x & 1;
    if (tile >= *nt_p) return;
    int c0 = half * 64;
    extern __shared__ __align__(16) char smem[];
    int*   sNode = (int*)smem;
    float* sBias = (float*)(smem + 512);
    uint32_t sbase = smem_u32(smem);
    int t = threadIdx.x;
    int j = tg[tile], b0 = tb[tile];
    int mc = off[j + 1] - b0; if (mc > 64) mc = 64;
    if (t < 64)  sNode[t] = perm[b0 + min(t, mc - 1)];
    if (t < 64)  sBias[t] = bias[j * 128 + c0 + t];
    __syncthreads();

    // W staging via cp.async: WT rows e in [c0, c0+64), hi & lo (32KB total)
    {
        const uint4* srcH = (const uint4*)(g_wsp + (size_t)(woff + j) * 32768) + c0 * 16;
        const uint4* srcL = (const uint4*)(g_wsp + (size_t)(woff + j) * 32768 + 16384) + c0 * 16;
#pragma unroll
        for (int i = 0; i < 4; ++i) {
            int idx = t + 256 * i;            // 0..1023 uint4
            int r = idx >> 4, c = idx & 15;   // local row e, 16B chunk
            cpasync16(sbase + OFF_WH + r * TROW + 16 * c, srcH + idx);
            cpasync16(sbase + OFF_WL + r * TROW + 16 * c, srcL + idx);
        }
        asm volatile("cp.async.commit_group;");
    }
    // A staging: gather row (+max over kids), split hi/lo
    {
        const float4* X4 = (const float4*)srcA;
        const float4* U4 = (const float4*)g_u;
#pragma unroll
        for (int i = 0; i < 8; ++i) {
            int idx = t + 256 * i;            // 0..2047
            int r = idx >> 5, c = idx & 31;
            int node = sNode[r];
            float4 v = X4[(size_t)node * 32 + c];
            if (mode == 2) {
                int ch = cs_child + 4 * (node - cs_row);
                v = max4(v, U4[(size_t)(ch + 0) * 32 + c]);
                v = max4(v, U4[(size_t)(ch + 1) * 32 + c]);
                v = max4(v, U4[(size_t)(ch + 2) * 32 + c]);
                v = max4(v, U4[(size_t)(ch + 3) * 32 + c]);
            }
            __nv_bfloat16 h0 = __float2bfloat16(v.x), h1 = __float2bfloat16(v.y);
            __nv_bfloat16 h2 = __float2bfloat16(v.z), h3 = __float2bfloat16(v.w);
            __nv_bfloat162 ha; ha.x = h0; ha.y = h1;
            __nv_bfloat162 hb; hb.x = h2; hb.y = h3;
            __nv_bfloat162 la, lb;
            la.x = __float2bfloat16(v.x - __bfloat162float(h0));
            la.y = __float2bfloat16(v.y - __bfloat162float(h1));
            lb.x = __float2bfloat16(v.z - __bfloat162float(h2));
            lb.y = __float2bfloat16(v.w - __bfloat162float(h3));
            uint2 hh; hh.x = *(uint32_t*)&ha; hh.y = *(uint32_t*)&hb;
            uint2 ll; ll.x = *(uint32_t*)&la; ll.y = *(uint32_t*)&lb;
            *(uint2*)(smem + OFF_AH + r * TROW + 8 * c) = hh;
            *(uint2*)(smem + OFF_AL + r * TROW + 8 * c) = ll;
        }
    }
    asm volatile("cp.async.wait_group 0;" ::: "memory");
    __syncthreads();

    int lane = t & 31, warp = t >> 5;
    int g = lane >> 2, tid = lane & 3;
    int m0 = (warp & 1) * 32, n0 = (warp >> 1) * 16;   // local col base

    float acc[2][2][4];
#pragma unroll
    for (int mt = 0; mt < 2; ++mt)
#pragma unroll
        for (int nt = 0; nt < 2; ++nt)
#pragma unroll
            for (int q = 0; q < 4; ++q) acc[mt][nt][q] = 0.f;

    const uint32_t* Ah = (const uint32_t*)(smem + OFF_AH);
    const uint32_t* Al = (const uint32_t*)(smem + OFF_AL);
    const uint32_t* Wh = (const uint32_t*)(smem + OFF_WH);
    const uint32_t* Wl = (const uint32_t*)(smem + OFF_WL);

#pragma unroll
    for (int pass = 0; pass < 3; ++pass) {
        const uint32_t* As = (pass == 2) ? Al : Ah;
        const uint32_t* Ws = (pass == 1) ? Wl : Wh;
#pragma unroll
        for (int k16 = 0; k16 < 8; ++k16) {
            int kb = k16 * 8;
            uint32_t a[2][4];
#pragma unroll
            for (int mt = 0; mt < 2; ++mt) {
                int r = m0 + 16 * mt;
                a[mt][0] = As[(r + g) * TSTR + kb + tid];
                a[mt][1] = As[(r + g + 8) * TSTR + kb + tid];
                a[mt][2] = As[(r + g) * TSTR + kb + tid + 4];
                a[mt][3] = As[(r + g + 8) * TSTR + kb + tid + 4];
            }
#pragma unroll
            for (int nt = 0; nt < 2; ++nt) {
                int e = n0 + 8 * nt + g;          // local col
                uint32_t bb0 = Ws[e * TSTR + kb + tid];
                uint32_t bb1 = Ws[e * TSTR + kb + tid + 4];
                mma16816(acc[0][nt][0], acc[0][nt][1], acc[0][nt][2], acc[0][nt][3],
                         a[0][0], a[0][1], a[0][2], a[0][3], bb0, bb1);
                mma16816(acc[1][nt][0], acc[1][nt][1], acc[1][nt][2], acc[1][nt][3],
                         a[1][0], a[1][1], a[1][2], a[1][3], bb0, bb1);
            }
        }
    }

    float* base = (mode == 0) ? g_xz : g_u;
#pragma unroll
    for (int mt = 0; mt < 2; ++mt) {
        int row = m0 + 16 * mt + g;
        int nodeA = sNode[row];
        int nodeB = sNode[row + 8];
#pragma unroll
        for (int nt = 0; nt < 2; ++nt) {
            int cl = n0 + 8 * nt + 2 * tid;       // local col
            float bx = sBias[cl], by = sBias[cl + 1];
            float2 oA, oB;
            oA.x = fmaxf(acc[mt][nt][0] + bx, 0.f);
            oA.y = fmaxf(acc[mt][nt][1] + by, 0.f);
            oB.x = fmaxf(acc[mt][nt][2] + bx, 0.f);
            oB.y = fmaxf(acc[mt][nt][3] + by, 0.f);
            *(float2*)&base[(size_t)nodeA * 128 + c0 + cl] = oA;
            *(float2*)&base[(size_t)nodeB * 128 + c0 + cl] = oB;
        }
    }
}

// ---------------------------------------------------------------------------
// Narrow persistent kernel: dep levels 3..0 (packed-k FFMA2), root finalize.
// ---------------------------------------------------------------------------
__global__ __launch_bounds__(256, 2)
void narrow_all(const float* __restrict__ Wsrc, const float* __restrict__ bias,
                float* __restrict__ out)
{
    __shared__ __align__(16) char sWn[64 * 256];
    __shared__ __align__(16) float sA2[16 * 128];
    __shared__ int sN[16];
    int t = threadIdx.x;
    int nb = gridDim.x;
    for (int l = 3; l >= 0; --l) {
        int cs_row = lvl_start(l + 1);
        int cs_child = lvl_start(l + 2);
        int nt = g_dep_nt[l];
        int items = nt * 4;
        const int* tg = g_dep_tg[l];
        const int* tb = g_dep_tb[l];
        const int* off = g_dep_off[l];
        for (int item = blockIdx.x; item < items; item += nb) {
            __syncthreads();
            int tile = item >> 2, slice = item & 3, c0 = slice * 32;
            int j = tg[tile], b0 = tb[tile];
            int mc = off[j + 1] - b0; if (mc > 16) mc = 16;
            if (t < 16) sN[t] = g_dep_perm[cs_row + b0 + min(t, mc - 1)];
            const float* Wj = Wsrc + (size_t)j * 16384;
#pragma unroll
            for (int i = 0; i < 2; ++i) {
                int idx = t + 256 * i;
                int kp = idx >> 3, cb = idx & 7;
                float4 r0 = *(const float4*)&Wj[(2 * kp) * 128 + c0 + 4 * cb];
                float4 r1 = *(const float4*)&Wj[(2 * kp + 1) * 128 + c0 + 4 * cb];
                float4 s0 = make_float4(r0.x, r1.x, r0.y, r1.y);
                float4 s1 = make_float4(r0.z, r1.z, r0.w, r1.w);
                unsigned b = (unsigned)(kp * 256 + cb * 32);
                *(float4*)(sWn + sw16(b))      = s0;
                *(float4*)(sWn + sw16(b + 16)) = s1;
            }
            __syncthreads();
            const float4* X4 = (const float4*)g_xz;
            const float4* U4 = (const float4*)g_u;
#pragma unroll
            for (int i = 0; i < 2; ++i) {
                int idx = t + 256 * i; int r = idx >> 5, c = idx & 31;
                int node = sN[r];
                int ch = cs_child + 4 * (node - cs_row);
                float4 v = X4[(size_t)node * 32 + c];
                v = max4(v, U4[(size_t)(ch + 0) * 32 + c]);
                v = max4(v, U4[(size_t)(ch + 1) * 32 + c]);
                v = max4(v, U4[(size_t)(ch + 2) * 32 + c]);
                v = max4(v, U4[(size_t)(ch + 3) * 32 + c]);
                ((float4*)(sA2 + r * 128))[c] = v;
            }
            __syncthreads();
            int r = t >> 4, x16 = t & 15;
            ull accA = 0ull, accB = 0ull;
#pragma unroll 4
            for (int kp = 0; kp < 64; ++kp) {
                ull a = *(const ull*)&sA2[r * 128 + 2 * kp];
                ulonglong2 w = *(const ulonglong2*)(sWn + sw16((unsigned)(kp * 256 + x16 * 16)));
                fma2(accA, a, w.x);
                fma2(accB, a, w.y);
            }
            int node = sN[r];
            int col = c0 + 2 * x16;
            float2 bv = *(const float2*)&bias[j * 128 + col];
            float lo, hi; float2 o;
            unpack2(accA, lo, hi); o.x = fmaxf(lo + hi + bv.x, 0.f);
            unpack2(accB, lo, hi); o.y = fmaxf(lo + hi + bv.y, 0.f);
            *(float2*)&g_u[(size_t)node * 128 + col] = o;
        }
        gridbar(nb);
    }
    if (blockIdx.x == 0 && t < 32) {
        const float4* X4 = (const float4*)g_xz;
        const float4* U4 = (const float4*)g_u;
        float4 v = X4[t];
        v = max4(v, U4[1 * 32 + t]);
        v = max4(v, U4[2 * 32 + t]);
        v = max4(v, U4[3 * 32 + t]);
        v = max4(v, U4[4 * 32 + t]);
        ((float4*)out)[t] = v;
    }
}

// ---------------------------------------------------------------------------
extern "C" void kernel_launch(void* const* d_in, const int* in_sizes, int n_in,
                              void* d_out, int out_size) {
    const float* emb     = (const float*)d_in[0];
    const int*   pos_ids = (const int*)d_in[1];
    const int*   dep_ids = (const int*)d_in[2];
    const float* pos_W   = (const float*)d_in[3];
    const float* pos_b   = (const float*)d_in[4];
    const float* dep_W   = (const float*)d_in[5];
    const float* dep_b   = (const float*)d_in[6];

    cudaFuncSetAttribute(tile_mma, cudaFuncAttributeMaxDynamicSharedMemorySize,
                         SMEM_T);

    int *d_pos_nt, *d_pos_tg, *d_pos_tb, *d_pos_off, *d_pos_perm;
    int *d_dep_nt, *d_dep_tg, *d_dep_tb, *d_dep_off, *d_dep_perm;
    cudaGetSymbolAddress((void**)&d_pos_nt,   g_pos_nt);
    cudaGetSymbolAddress((void**)&d_pos_tg,   g_pos_tg);
    cudaGetSymbolAddress((void**)&d_pos_tb,   g_pos_tb);
    cudaGetSymbolAddress((void**)&d_pos_off,  g_pos_off);
    cudaGetSymbolAddress((void**)&d_pos_perm, g_pos_perm);
    cudaGetSymbolAddress((void**)&d_dep_nt,   g_dep_nt);
    cudaGetSymbolAddress((void**)&d_dep_tg,   g_dep_tg);
    cudaGetSymbolAddress((void**)&d_dep_tb,   g_dep_tb);
    cudaGetSymbolAddress((void**)&d_dep_off,  g_dep_off);
    cudaGetSymbolAddress((void**)&d_dep_perm, g_dep_perm);
    float* d_xz;
    cudaGetSymbolAddress((void**)&d_xz, g_xz);

    // grouping + W pre-split, one launch
    prep_kernel<<<8 + NMAT, 256>>>(pos_ids, dep_ids, pos_W, dep_W);

    // pos: all NN nodes -> g_xz  (tiles <= 360 -> 720 blocks)
    tile_mma<<<720, 256, SMEM_T>>>(0, 0, pos_b, emb,
        d_pos_nt, d_pos_tg, d_pos_tb, d_pos_off, d_pos_perm, 0, 0);

    // dep level 6 (z = x) -> g_u  (tiles <= 302 -> 604)
    tile_mma<<<604, 256, SMEM_T>>>(1, NPOS, dep_b, d_xz,
        d_dep_nt + 6, d_dep_tg + 6 * 320, d_dep_tb + 6 * 320,
        d_dep_off + 6 * (NDEP + 1), d_dep_perm + lvl_start(7),
        lvl_start(7), 0);

    // dep level 5 (max-gather) -> g_u  (tiles <= 110 -> 220)
    tile_mma<<<220, 256, SMEM_T>>>(2, NPOS, dep_b, d_xz,
        d_dep_nt + 5, d_dep_tg + 5 * 320, d_dep_tb + 5 * 320,
        d_dep_off + 5 * (NDEP + 1), d_dep_perm + lvl_start(6),
        lvl_start(6), lvl_start(7));

    // dep level 4 (max-gather) -> g_u  (tiles <= 62 -> 124)
    tile_mma<<<124, 256, SMEM_T>>>(2, NPOS, dep_b, d_xz,
        d_dep_nt + 4, d_dep_tg + 4 * 320, d_dep_tb + 4 * 320,
        d_dep_off + 4 * (NDEP + 1), d_dep_perm + lvl_start(5),
        lvl_start(5), lvl_start(6));

    // levels 3..0 + root finalize
    int dev = 0, nsm = 0, occ = 0;
    cudaGetDevice(&dev);
    cudaDeviceGetAttribute(&nsm, cudaDevAttrMultiProcessorCount, dev);
    cudaOccupancyMaxActiveBlocksPerMultiprocessor(&occ, narrow_all, 256, 0);
    if (occ < 1) occ = 1;
    int grid = nsm * (occ < 2 ? occ : 2);
    narrow_all<<<grid, 256>>>(dep_W, dep_b, (float*)d_out);
}

// round 15
// speedup vs baseline: 1.1203x; 1.1155x over previous
#include <cuda_runtime.h>
#include <cstdint>

#define DD   128
#define NN   21845          // (4^8 - 1) / 3
#define NPOS 18
#define NDEP 46

__host__ __device__ __forceinline__ int lvl_start(int l) {
    return ((1 << (2 * l)) - 1) / 3;
}

typedef unsigned long long ull;

// FFMA2 (packed f32x2), only reachable via PTX
__device__ __forceinline__ void fma2(ull& acc, ull a, ull b) {
    asm("fma.rn.f32x2 %0, %1, %2, %0;" : "+l"(acc) : "l"(a), "l"(b));
}
__device__ __forceinline__ void unpack2(ull v, float& lo, float& hi) {
    asm("mov.b64 {%0, %1}, %2;" : "=f"(lo), "=f"(hi) : "l"(v));
}
__device__ __forceinline__ float4 max4(float4 a, float4 b) {
    float4 r;
    r.x = fmaxf(a.x, b.x); r.y = fmaxf(a.y, b.y);
    r.z = fmaxf(a.z, b.z); r.w = fmaxf(a.w, b.w);
    return r;
}
// XOR swizzle: makes 32B-stride 16B smem accesses conflict-free
__device__ __forceinline__ unsigned sw16(unsigned b) {
    return b ^ ((b >> 3) & 0x10u);
}
__device__ __forceinline__ uint32_t smem_u32(const void* p) {
    uint32_t a;
    asm("{ .reg .u64 t; cvta.to.shared.u64 t, %1; cvt.u32.u64 %0, t; }"
        : "=r"(a) : "l"(p));
    return a;
}
__device__ __forceinline__ void cpasync16(uint32_t dst, const void* src) {
    asm volatile("cp.async.cg.shared.global [%0], [%1], 16;"
                 :: "r"(dst), "l"(src));
}

// ---------------- persistent scratch ----------------
__device__ float g_xz[NN * DD];            // x from pos stage
__device__ float g_u[NN * DD];             // u outputs keyed by global child idx
__device__ int   g_pos_perm[NN];
__device__ int   g_pos_off[NPOS + 1];
__device__ int   g_pos_tg[384], g_pos_tb[384];
__device__ int   g_pos_nt;
__device__ int   g_dep_perm[NN];
__device__ int   g_dep_off[7][NDEP + 1];
__device__ int   g_dep_tg[7][320], g_dep_tb[7][320];
__device__ int   g_dep_nt[7];
__device__ unsigned g_bar_cnt;
__device__ unsigned g_bar_gen;

__device__ __forceinline__ void gridbar(int nb) {
    __syncthreads();
    if (threadIdx.x == 0) {
        __threadfence();
        unsigned gen = *(volatile unsigned*)&g_bar_gen;
        if (atomicAdd(&g_bar_cnt, 1u) == (unsigned)nb - 1u) {
            atomicExch(&g_bar_cnt, 0u);
            __threadfence();
            atomicAdd(&g_bar_gen, 1u);
        } else {
            while (*(volatile unsigned*)&g_bar_gen == gen) __nanosleep(64);
        }
        __threadfence();
    }
    __syncthreads();
}

// ---------------------------------------------------------------------------
// Grouping: block 0 = pos, blocks 1..7 = dep level b-1
// ---------------------------------------------------------------------------
__global__ void group_kernel(const int* __restrict__ pos_ids,
                             const int* __restrict__ dep_ids) {
    __shared__ int cnt[NDEP];
    __shared__ int off[NDEP + 1];
    int t = threadIdx.x, lane = t & 31;
    const int* ids; int n, ng, base, BM;
    int *perm, *goff, *tg, *tb, *nt_out;
    if (blockIdx.x == 0) {
        ids = pos_ids; n = NN; ng = NPOS; base = 0; BM = 64;
        perm = g_pos_perm; goff = g_pos_off;
        tg = g_pos_tg; tb = g_pos_tb; nt_out = &g_pos_nt;
    } else {
        int l = blockIdx.x - 1;
        base = lvl_start(l + 1); n = 1 << (2 * (l + 1)); ng = NDEP;
        BM = (l >= 5) ? 64 : 16;
        ids = dep_ids + base; perm = g_dep_perm + base; goff = g_dep_off[l];
        tg = g_dep_tg[l]; tb = g_dep_tb[l]; nt_out = &g_dep_nt[l];
    }
    if (t < ng) cnt[t] = 0;
    __syncthreads();
    for (int i0 = 0; i0 < n; i0 += blockDim.x) {
        int i = i0 + t; bool v = (i < n);
        unsigned act = __ballot_sync(0xffffffffu, v);
        if (v) {
            int id = ids[i];
            unsigned m = __match_any_sync(act, id);
            if (lane == __ffs(m) - 1) atomicAdd(&cnt[id], __popc(m));
        }
    }
    __syncthreads();
    if (t == 0) {
        int s = 0;
        for (int j = 0; j < ng; ++j) { off[j] = s; s += cnt[j]; }
        off[ng] = s;
        int nt = 0;
        for (int j = 0; j < ng; ++j) {
            int c = off[j + 1] - off[j];
            for (int k = 0; k < c; k += BM) { tg[nt] = j; tb[nt] = off[j] + k; ++nt; }
        }
        *nt_out = nt;
        for (int j = 0; j <= ng; ++j) goff[j] = off[j];
    }
    __syncthreads();
    if (t < ng) cnt[t] = off[t];
    __syncthreads();
    for (int i0 = 0; i0 < n; i0 += blockDim.x) {
        int i = i0 + t; bool v = (i < n);
        unsigned act = __ballot_sync(0xffffffffu, v);
        if (v) {
            int id = ids[i];
            unsigned m = __match_any_sync(act, id);
            int leader = __ffs(m) - 1;
            int prior = __popc(m & ((1u << lane) - 1u));
            int bp = 0;
            if (lane == leader) bp = atomicAdd(&cnt[id], __popc(m));
            bp = __shfl_sync(act, bp, leader);
            perm[bp + prior] = base + i;
        }
    }
}

// ---------------------------------------------------------------------------
// Big grouped GEMM (R6 core): BM=64 x BN=128, K=128, 256 threads, 2 CTAs/SM.
// Packed-k FFMA2; W smem pair-major interleaved, built from cp.async-staged
// raw W rows? No — R6 built pairs inline. Here: W raw rows cp.async'd into a
// scratch region (overlapped with A gather), then pair-interleaved into sWb.
// mode 0: A=emb -> g_xz ; mode 1: A=g_xz -> g_u ; mode 2: A=maxgather -> g_u
// smem: sWb 64KB pair-major | sA 32KB | sWraw reuses sA? No: need both.
// Layout: sWb 65536 | sA 32768 | (sWraw overlaps sWb build source = global)
// To keep identical math to R6 while overlapping, we cp.async W rows into a
// 64KB raw region, A-gather concurrently, then one smem->smem interleave pass.
// smem total = 65536(sWb) + 32768(sA) = 98304; raw W staged INTO sWb space
// first (linear), then interleaved in-place is unsafe -> instead interleave
// from raw (placed in sWb) into sA? sA needed too. Simplest safe: raw W goes
// to sWb linearly; the FFMA2 loop reads RAW row-major W exactly like R6's
// build did, i.e. we keep R6's pair-major build but source from smem (fast,
// no global latency) after cp.async lands.
// ---------------------------------------------------------------------------
#define SMEM_BIG (65536 + 64 * 128 * 4 + 1024)

__global__ __launch_bounds__(256, 2)
void gemm_big(int mode, const float* __restrict__ Wsrc,
              const float* __restrict__ bias, const float* __restrict__ srcA,
              const int* __restrict__ nt_p, const int* __restrict__ tg,
              const int* __restrict__ tb, const int* __restrict__ off,
              const int* __restrict__ perm, int cs_row, int cs_child)
{
    int tile = blockIdx.x;
    if (tile >= *nt_p) return;
    extern __shared__ __align__(16) char smc[];
    char*  sWb = smc;                        // 64KB pair-major W (final)
    float* sA  = (float*)(smc + 65536);      // 64x128 row-major A
    int*   sNode = (int*)(smc + 65536 + 32768);
    int t = threadIdx.x;
    int j = tg[tile], b0 = tb[tile];
    int mc = off[j + 1] - b0; if (mc > 64) mc = 64;
    if (t < 64) sNode[t] = perm[b0 + min(t, mc - 1)];
    __syncthreads();

    // --- stage 1: cp.async raw W (64KB) into sWb linearly; A gather overlaps ---
    uint32_t sbase = smem_u32(smc);
    {
        const uint4* W16 = (const uint4*)(Wsrc + (size_t)j * 16384);
#pragma unroll
        for (int i = 0; i < 16; ++i)
            cpasync16(sbase + (t + 256 * i) * 16, W16 + t + 256 * i);
        asm volatile("cp.async.commit_group;");
    }
    if (mode < 2) {
        const float4* A4 = (const float4*)srcA;
#pragma unroll
        for (int i = 0; i < 8; ++i) {
            int idx = t + 256 * i; int r = idx >> 5, c = idx & 31;
            ((float4*)(sA + r * 128))[c] = A4[(size_t)sNode[r] * 32 + c];
        }
    } else {
        const float4* X4 = (const float4*)g_xz;
        const float4* U4 = (const float4*)g_u;
#pragma unroll
        for (int i = 0; i < 8; ++i) {
            int idx = t + 256 * i; int r = idx >> 5, c = idx & 31;
            int node = sNode[r];
            int ch = cs_child + 4 * (node - cs_row);
            float4 v = X4[(size_t)node * 32 + c];
            v = max4(v, U4[(size_t)(ch + 0) * 32 + c]);
            v = max4(v, U4[(size_t)(ch + 1) * 32 + c]);
            v = max4(v, U4[(size_t)(ch + 2) * 32 + c]);
            v = max4(v, U4[(size_t)(ch + 3) * 32 + c]);
            ((float4*)(sA + r * 128))[c] = v;
        }
    }
    asm volatile("cp.async.wait_group 0;" ::: "memory");
    __syncthreads();

    // --- stage 2: in-smem pair-major interleave of W ---
    // raw layout: row k (128 floats) at sWb + k*512.
    // target chunk(kp, cb): {w(2kp,4cb..), w(2kp+1,4cb..)} interleaved, swizzled.
    // In-place rebuild is unsafe; interleave into registers for OWN chunks only:
    // each thread handles 8 chunk-pairs: reads raw, then after a sync writes.
    {
        float4 s0[8], s1[8];
        unsigned boffs[8];
#pragma unroll
        for (int i = 0; i < 8; ++i) {
            int idx = t + 256 * i;              // 0..2047
            int kp = idx >> 5, cb = idx & 31;
            const float4* r0p = (const float4*)(sWb + (2 * kp) * 512) + cb;
            const float4* r1p = (const float4*)(sWb + (2 * kp + 1) * 512) + cb;
            float4 r0 = *r0p, r1 = *r1p;
            s0[i] = make_float4(r0.x, r1.x, r0.y, r1.y);
            s1[i] = make_float4(r0.z, r1.z, r0.w, r1.w);
            boffs[i] = (unsigned)(kp * 1024 + cb * 32);
        }
        __syncthreads();    // all raw reads done before overwrite
#pragma unroll
        for (int i = 0; i < 8; ++i) {
            *(float4*)(sWb + sw16(boffs[i]))      = s0[i];
            *(float4*)(sWb + sw16(boffs[i] + 16)) = s1[i];
        }
    }
    __syncthreads();

    int tx = t & 31, ty = t >> 5;
    ull acc[8][4];
#pragma unroll
    for (int i = 0; i < 8; ++i)
#pragma unroll
        for (int q = 0; q < 4; ++q) acc[i][q] = 0ull;
#pragma unroll 2
    for (int k4 = 0; k4 < 32; ++k4) {
        unsigned wb0 = (unsigned)((2 * k4) * 1024 + tx * 32);
        unsigned wb1 = wb0 + 1024;
        ulonglong2 w0a = *(const ulonglong2*)(sWb + sw16(wb0));
        ulonglong2 w0b = *(const ulonglong2*)(sWb + sw16(wb0 + 16));
        ulonglong2 w1a = *(const ulonglong2*)(sWb + sw16(wb1));
        ulonglong2 w1b = *(const ulonglong2*)(sWb + sw16(wb1 + 16));
#pragma unroll
        for (int i = 0; i < 8; ++i) {
            ulonglong2 aa = *(const ulonglong2*)&sA[(ty + 8 * i) * 128 + 4 * k4];
            fma2(acc[i][0], aa.x, w0a.x);
            fma2(acc[i][1], aa.x, w0a.y);
            fma2(acc[i][2], aa.x, w0b.x);
            fma2(acc[i][3], aa.x, w0b.y);
            fma2(acc[i][0], aa.y, w1a.x);
            fma2(acc[i][1], aa.y, w1a.y);
            fma2(acc[i][2], aa.y, w1b.x);
            fma2(acc[i][3], aa.y, w1b.y);
        }
    }
    float4 bv = *(const float4*)&bias[j * 128 + 4 * tx];
    float* dst = (mode == 0) ? g_xz : g_u;
#pragma unroll
    for (int i = 0; i < 8; ++i) {
        int node = sNode[ty + 8 * i];
        float lo, hi; float4 o;
        unpack2(acc[i][0], lo, hi); o.x = fmaxf(lo + hi + bv.x, 0.f);
        unpack2(acc[i][1], lo, hi); o.y = fmaxf(lo + hi + bv.y, 0.f);
        unpack2(acc[i][2], lo, hi); o.z = fmaxf(lo + hi + bv.z, 0.f);
        unpack2(acc[i][3], lo, hi); o.w = fmaxf(lo + hi + bv.w, 0.f);
        *(float4*)&dst[(size_t)node * 128 + 4 * tx] = o;
    }
}

// ---------------------------------------------------------------------------
// Narrow persistent kernel: dep levels 4..0 (packed-k FFMA2), root finalize.
// ---------------------------------------------------------------------------
__global__ __launch_bounds__(256, 2)
void narrow_all(const float* __restrict__ Wsrc, const float* __restrict__ bias,
                float* __restrict__ out)
{
    __shared__ __align__(16) char sWn[64 * 256];    // 16KB pair-major W slice
    __shared__ __align__(16) float sA2[16 * 128];
    __shared__ int sN[16];
    int t = threadIdx.x;
    int nb = gridDim.x;
    for (int l = 4; l >= 0; --l) {
        int cs_row = lvl_start(l + 1);
        int cs_child = lvl_start(l + 2);
        int nt = g_dep_nt[l];
        int items = nt * 4;
        const int* tg = g_dep_tg[l];
        const int* tb = g_dep_tb[l];
        const int* off = g_dep_off[l];
        for (int item = blockIdx.x; item < items; item += nb) {
            __syncthreads();
            int tile = item >> 2, slice = item & 3, c0 = slice * 32;
            int j = tg[tile], b0 = tb[tile];
            int mc = off[j + 1] - b0; if (mc > 16) mc = 16;
            if (t < 16) sN[t] = g_dep_perm[cs_row + b0 + min(t, mc - 1)];
            const float* Wj = Wsrc + (size_t)j * 16384;
#pragma unroll
            for (int i = 0; i < 2; ++i) {
                int idx = t + 256 * i;
                int kp = idx >> 3, cb = idx & 7;
                float4 r0 = *(const float4*)&Wj[(2 * kp) * 128 + c0 + 4 * cb];
                float4 r1 = *(const float4*)&Wj[(2 * kp + 1) * 128 + c0 + 4 * cb];
                float4 s0 = make_float4(r0.x, r1.x, r0.y, r1.y);
                float4 s1 = make_float4(r0.z, r1.z, r0.w, r1.w);
                unsigned b = (unsigned)(kp * 256 + cb * 32);
                *(float4*)(sWn + sw16(b))      = s0;
                *(float4*)(sWn + sw16(b + 16)) = s1;
            }
            __syncthreads();
            const float4* X4 = (const float4*)g_xz;
            const float4* U4 = (const float4*)g_u;
#pragma unroll
            for (int i = 0; i < 2; ++i) {
                int idx = t + 256 * i; int r = idx >> 5, c = idx & 31;
                int node = sN[r];
                int ch = cs_child + 4 * (node - cs_row);
                float4 v = X4[(size_t)node * 32 + c];
                v = max4(v, U4[(size_t)(ch + 0) * 32 + c]);
                v = max4(v, U4[(size_t)(ch + 1) * 32 + c]);
                v = max4(v, U4[(size_t)(ch + 2) * 32 + c]);
                v = max4(v, U4[(size_t)(ch + 3) * 32 + c]);
                ((float4*)(sA2 + r * 128))[c] = v;
            }
            __syncthreads();
            int r = t >> 4, x16 = t & 15;
            ull accA = 0ull, accB = 0ull;
#pragma unroll 4
            for (int kp = 0; kp < 64; ++kp) {
                ull a = *(const ull*)&sA2[r * 128 + 2 * kp];
                ulonglong2 w = *(const ulonglong2*)(sWn + sw16((unsigned)(kp * 256 + x16 * 16)));
                fma2(accA, a, w.x);
                fma2(accB, a, w.y);
            }
            int node = sN[r];
            int col = c0 + 2 * x16;
            float2 bv = *(const float2*)&bias[j * 128 + col];
            float lo, hi; float2 o;
            unpack2(accA, lo, hi); o.x = fmaxf(lo + hi + bv.x, 0.f);
            unpack2(accB, lo, hi); o.y = fmaxf(lo + hi + bv.y, 0.f);
            *(float2*)&g_u[(size_t)node * 128 + col] = o;
        }
        gridbar(nb);
    }
    // root finalize: out = max(x[0], u of nodes 1..4)
    if (blockIdx.x == 0 && t < 32) {
        const float4* X4 = (const float4*)g_xz;
        const float4* U4 = (const float4*)g_u;
        float4 v = X4[t];
        v = max4(v, U4[1 * 32 + t]);
        v = max4(v, U4[2 * 32 + t]);
        v = max4(v, U4[3 * 32 + t]);
        v = max4(v, U4[4 * 32 + t]);
        ((float4*)out)[t] = v;
    }
}

// ---------------------------------------------------------------------------
extern "C" void kernel_launch(void* const* d_in, const int* in_sizes, int n_in,
                              void* d_out, int out_size) {
    const float* emb     = (const float*)d_in[0];
    const int*   pos_ids = (const int*)d_in[1];
    const int*   dep_ids = (const int*)d_in[2];
    const float* pos_W   = (const float*)d_in[3];
    const float* pos_b   = (const float*)d_in[4];
    const float* dep_W   = (const float*)d_in[5];
    const float* dep_b   = (const float*)d_in[6];

    cudaFuncSetAttribute(gemm_big, cudaFuncAttributeMaxDynamicSharedMemorySize,
                         SMEM_BIG);

    int *d_pos_nt, *d_pos_tg, *d_pos_tb, *d_pos_off, *d_pos_perm;
    int *d_dep_nt, *d_dep_tg, *d_dep_tb, *d_dep_off, *d_dep_perm;
    cudaGetSymbolAddress((void**)&d_pos_nt,   g_pos_nt);
    cudaGetSymbolAddress((void**)&d_pos_tg,   g_pos_tg);
    cudaGetSymbolAddress((void**)&d_pos_tb,   g_pos_tb);
    cudaGetSymbolAddress((void**)&d_pos_off,  g_pos_off);
    cudaGetSymbolAddress((void**)&d_pos_perm, g_pos_perm);
    cudaGetSymbolAddress((void**)&d_dep_nt,   g_dep_nt);
    cudaGetSymbolAddress((void**)&d_dep_tg,   g_dep_tg);
    cudaGetSymbolAddress((void**)&d_dep_tb,   g_dep_tb);
    cudaGetSymbolAddress((void**)&d_dep_off,  g_dep_off);
    cudaGetSymbolAddress((void**)&d_dep_perm, g_dep_perm);
    float* d_xz;
    cudaGetSymbolAddress((void**)&d_xz, g_xz);

    group_kernel<<<8, 1024>>>(pos_ids, dep_ids);

    // pos: all NN nodes -> g_xz
    gemm_big<<<360, 256, SMEM_BIG>>>(0, pos_W, pos_b, emb,
        d_pos_nt, d_pos_tg, d_pos_tb, d_pos_off, d_pos_perm, 0, 0);

    // dep level 6: rows = level-7 nodes (z = x), u -> g_u
    gemm_big<<<302, 256, SMEM_BIG>>>(1, dep_W, dep_b, d_xz,
        d_dep_nt + 6, d_dep_tg + 6 * 320, d_dep_tb + 6 * 320,
        d_dep_off + 6 * (NDEP + 1), d_dep_perm + lvl_start(7),
        lvl_start(7), 0);

    // dep level 5: rows = level-6 nodes, fused max-gather, u -> g_u
    gemm_big<<<110, 256, SMEM_BIG>>>(2, dep_W, dep_b, d_xz,
        d_dep_nt + 5, d_dep_tg + 5 * 320, d_dep_tb + 5 * 320,
        d_dep_off + 5 * (NDEP + 1), d_dep_perm + lvl_start(6),
        lvl_start(6), lvl_start(7));

    // levels 4..0 + root finalize in one persistent kernel
    int dev = 0, nsm = 0, occ = 0;
    cudaGetDevice(&dev);
    cudaDeviceGetAttribute(&nsm, cudaDevAttrMultiProcessorCount, dev);
    cudaOccupancyMaxActiveBlocksPerMultiprocessor(&occ, narrow_all, 256, 0);
    if (occ < 1) occ = 1;
    int grid = nsm * (occ < 2 ? occ : 2);
    narrow_all<<<grid, 256>>>(dep_W, dep_b, (float*)d_out);
}

// round 16
// speedup vs baseline: 1.1598x; 1.0353x over previous
#include <cuda_runtime.h>

#define DD   128
#define NN   21845          // (4^8 - 1) / 3
#define NPOS 18
#define NDEP 46
#define CS6  5461           // level_start(7)

__host__ __device__ __forceinline__ int lvl_start(int l) {
    return ((1 << (2 * l)) - 1) / 3;
}

typedef unsigned long long ull;

// packed f32x2 helpers (FFMA2: only reachable via PTX fma.rn.f32x2)
__device__ __forceinline__ void fma2(ull& acc, ull a, ull b) {
    asm("fma.rn.f32x2 %0, %1, %2, %0;" : "+l"(acc) : "l"(a), "l"(b));
}
__device__ __forceinline__ void unpack2(ull v, float& lo, float& hi) {
    asm("mov.b64 {%0, %1}, %2;" : "=f"(lo), "=f"(hi) : "l"(v));
}
__device__ __forceinline__ float4 max4(float4 a, float4 b) {
    float4 r;
    r.x = fmaxf(a.x, b.x); r.y = fmaxf(a.y, b.y);
    r.z = fmaxf(a.z, b.z); r.w = fmaxf(a.w, b.w);
    return r;
}
// XOR swizzle: makes 32B-stride 16B smem accesses conflict-free
__device__ __forceinline__ unsigned sw16(unsigned b) {
    return b ^ ((b >> 3) & 0x10u);
}

// persistent scratch (device globals: allocation-free)
__device__ float g_xz[NN * DD];            // x from pos stage
__device__ float g_u[NN * DD];             // u outputs keyed by global child idx
__device__ int   g_pos_perm[NN];
__device__ int   g_pos_off[NPOS + 1];
__device__ int   g_pos_tg[384], g_pos_tb[384];
__device__ int   g_pos_nt;
__device__ int   g_dep_perm[NN];
__device__ int   g_dep_off[7][NDEP + 1];
__device__ int   g_dep_tg[7][320], g_dep_tb[7][320];
__device__ int   g_dep_nt[7];
// grid barrier: cnt returns to 0; gen monotonic -> replay-safe
__device__ unsigned g_bar_cnt;
__device__ unsigned g_bar_gen;

__device__ __forceinline__ void gridbar(int nb) {
    __syncthreads();
    if (threadIdx.x == 0) {
        __threadfence();
        unsigned gen = *(volatile unsigned*)&g_bar_gen;
        if (atomicAdd(&g_bar_cnt, 1u) == (unsigned)nb - 1u) {
            atomicExch(&g_bar_cnt, 0u);
            __threadfence();
            atomicAdd(&g_bar_gen, 1u);
        } else {
            while (*(volatile unsigned*)&g_bar_gen == gen) __nanosleep(64);
        }
        __threadfence();
    }
    __syncthreads();
}

// ---------------------------------------------------------------------------
// Grouping: block 0 = pos, blocks 1..7 = dep level b-1
// ---------------------------------------------------------------------------
__global__ void group_kernel(const int* __restrict__ pos_ids,
                             const int* __restrict__ dep_ids) {
    __shared__ int cnt[NDEP];
    __shared__ int off[NDEP + 1];
    int t = threadIdx.x, lane = t & 31;
    const int* ids; int n, ng, base, BM;
    int *perm, *goff, *tg, *tb, *nt_out;
    if (blockIdx.x == 0) {
        ids = pos_ids; n = NN; ng = NPOS; base = 0; BM = 64;
        perm = g_pos_perm; goff = g_pos_off;
        tg = g_pos_tg; tb = g_pos_tb; nt_out = &g_pos_nt;
    } else {
        int l = blockIdx.x - 1;
        base = lvl_start(l + 1); n = 1 << (2 * (l + 1)); ng = NDEP;
        BM = (l >= 5) ? 64 : 16;
        ids = dep_ids + base; perm = g_dep_perm + base; goff = g_dep_off[l];
        tg = g_dep_tg[l]; tb = g_dep_tb[l]; nt_out = &g_dep_nt[l];
    }
    if (t < ng) cnt[t] = 0;
    __syncthreads();
    for (int i0 = 0; i0 < n; i0 += blockDim.x) {
        int i = i0 + t; bool v = (i < n);
        unsigned act = __ballot_sync(0xffffffffu, v);
        if (v) {
            int id = ids[i];
            unsigned m = __match_any_sync(act, id);
            if (lane == __ffs(m) - 1) atomicAdd(&cnt[id], __popc(m));
        }
    }
    __syncthreads();
    if (t == 0) {
        int s = 0;
        for (int j = 0; j < ng; ++j) { off[j] = s; s += cnt[j]; }
        off[ng] = s;
        int nt = 0;
        for (int j = 0; j < ng; ++j) {
            int c = off[j + 1] - off[j];
            for (int k = 0; k < c; k += BM) { tg[nt] = j; tb[nt] = off[j] + k; ++nt; }
        }
        *nt_out = nt;
        for (int j = 0; j <= ng; ++j) goff[j] = off[j];
    }
    __syncthreads();
    if (t < ng) cnt[t] = off[t];
    __syncthreads();
    for (int i0 = 0; i0 < n; i0 += blockDim.x) {
        int i = i0 + t; bool v = (i < n);
        unsigned act = __ballot_sync(0xffffffffu, v);
        if (v) {
            int id = ids[i];
            unsigned m = __match_any_sync(act, id);
            int leader = __ffs(m) - 1;
            int prior = __popc(m & ((1u << lane) - 1u));
            int bp = 0;
            if (lane == leader) bp = atomicAdd(&cnt[id], __popc(m));
            bp = __shfl_sync(act, bp, leader);
            perm[bp + prior] = base + i;
        }
    }
}

// ---------------------------------------------------------------------------
// Big grouped GEMM: BM=64 x BN=128, K=128, 256 threads, 2 CTAs/SM.
// Packed-k FFMA2: acc[row][col] pairs over (k, k+1); no ALU movs.
// W smem is pair-major interleaved: chunk(kp, c0=4cb) = 2 float4s
//   {w_k,c0, w_k+1,c0, w_k,c1, w_k+1,c1}, {c2,c3...}, XOR-swizzled.
// mode 0: A=emb -> g_xz ; mode 1: A=g_xz -> g_u ; mode 2: A=maxgather -> g_u
// ---------------------------------------------------------------------------
#define SMEM_BIG (65536 + 64 * 128 * 4)

__global__ __launch_bounds__(256, 2)
void gemm_big(int mode, const float* __restrict__ Wsrc,
              const float* __restrict__ bias, const float* __restrict__ srcA,
              const int* __restrict__ nt_p, const int* __restrict__ tg,
              const int* __restrict__ tb, const int* __restrict__ off,
              const int* __restrict__ perm, int cs_row, int cs_child)
{
    int tile = blockIdx.x;
    if (tile >= *nt_p) return;
    extern __shared__ __align__(16) char smc[];
    char*  sWb = smc;                        // 64KB pair-major W
    float* sA  = (float*)(smc + 65536);      // 64x128 row-major A
    __shared__ int sNode[64];
    int t = threadIdx.x;
    int j = tg[tile], b0 = tb[tile];
    int mc = off[j + 1] - b0; if (mc > 64) mc = 64;
    if (t < 64) sNode[t] = perm[b0 + min(t, mc - 1)];
    // --- W staging: pair-major interleave ---
    const float4* W4 = (const float4*)(Wsrc + (size_t)j * 16384);
#pragma unroll
    for (int i = 0; i < 8; ++i) {
        int idx = t + 256 * i;               // 0..2047
        int kp = idx >> 5, cb = idx & 31;
        float4 r0 = W4[64 * kp + cb];        // row 2kp,   cols 4cb..
        float4 r1 = W4[64 * kp + 32 + cb];   // row 2kp+1
        float4 s0 = make_float4(r0.x, r1.x, r0.y, r1.y);
        float4 s1 = make_float4(r0.z, r1.z, r0.w, r1.w);
        unsigned b = (unsigned)(kp * 1024 + cb * 32);
        *(float4*)(sWb + sw16(b))      = s0;
        *(float4*)(sWb + sw16(b + 16)) = s1;
    }
    __syncthreads();
    // --- A staging ---
    if (mode < 2) {
        const float4* A4 = (const float4*)srcA;
#pragma unroll
        for (int i = 0; i < 8; ++i) {
            int idx = t + 256 * i; int r = idx >> 5, c = idx & 31;
            ((float4*)(sA + r * 128))[c] = A4[(size_t)sNode[r] * 32 + c];
        }
    } else {
        const float4* X4 = (const float4*)g_xz;
        const float4* U4 = (const float4*)g_u;
#pragma unroll
        for (int i = 0; i < 8; ++i) {
            int idx = t + 256 * i; int r = idx >> 5, c = idx & 31;
            int node = sNode[r];
            int ch = cs_child + 4 * (node - cs_row);
            float4 v = X4[(size_t)node * 32 + c];
            v = max4(v, U4[(size_t)(ch + 0) * 32 + c]);
            v = max4(v, U4[(size_t)(ch + 1) * 32 + c]);
            v = max4(v, U4[(size_t)(ch + 2) * 32 + c]);
            v = max4(v, U4[(size_t)(ch + 3) * 32 + c]);
            ((float4*)(sA + r * 128))[c] = v;
        }
    }
    __syncthreads();
    int tx = t & 31, ty = t >> 5;
    ull acc[8][4];
#pragma unroll
    for (int i = 0; i < 8; ++i)
#pragma unroll
        for (int q = 0; q < 4; ++q) acc[i][q] = 0ull;
#pragma unroll 2
    for (int k4 = 0; k4 < 32; ++k4) {
        // W chunks for kpairs 2k4 and 2k4+1, cols 4tx..4tx+3
        unsigned wb0 = (unsigned)((2 * k4) * 1024 + tx * 32);
        unsigned wb1 = wb0 + 1024;
        ulonglong2 w0a = *(const ulonglong2*)(sWb + sw16(wb0));
        ulonglong2 w0b = *(const ulonglong2*)(sWb + sw16(wb0 + 16));
        ulonglong2 w1a = *(const ulonglong2*)(sWb + sw16(wb1));
        ulonglong2 w1b = *(const ulonglong2*)(sWb + sw16(wb1 + 16));
#pragma unroll
        for (int i = 0; i < 8; ++i) {
            ulonglong2 aa = *(const ulonglong2*)&sA[(ty + 8 * i) * 128 + 4 * k4];
            fma2(acc[i][0], aa.x, w0a.x);
            fma2(acc[i][1], aa.x, w0a.y);
            fma2(acc[i][2], aa.x, w0b.x);
            fma2(acc[i][3], aa.x, w0b.y);
            fma2(acc[i][0], aa.y, w1a.x);
            fma2(acc[i][1], aa.y, w1a.y);
            fma2(acc[i][2], aa.y, w1b.x);
            fma2(acc[i][3], aa.y, w1b.y);
        }
    }
    float4 bv = *(const float4*)&bias[j * 128 + 4 * tx];
    float* dst = (mode == 0) ? g_xz : g_u;
#pragma unroll
    for (int i = 0; i < 8; ++i) {
        int node = sNode[ty + 8 * i];
        float lo, hi; float4 o;
        unpack2(acc[i][0], lo, hi); o.x = fmaxf(lo + hi + bv.x, 0.f);
        unpack2(acc[i][1], lo, hi); o.y = fmaxf(lo + hi + bv.y, 0.f);
        unpack2(acc[i][2], lo, hi); o.z = fmaxf(lo + hi + bv.z, 0.f);
        unpack2(acc[i][3], lo, hi); o.w = fmaxf(lo + hi + bv.w, 0.f);
        *(float4*)&dst[(size_t)node * 128 + 4 * tx] = o;
    }
}

// ---------------------------------------------------------------------------
// Narrow persistent kernel: dep levels 4..0 (packed-k FFMA2), root finalize.
// item = (16-row tile) x (32-col slice); 256 thr: 16 rows x 16 thr x 2 cols.
// ---------------------------------------------------------------------------
__global__ __launch_bounds__(256, 2)
void narrow_all(const float* __restrict__ Wsrc, const float* __restrict__ bias,
                float* __restrict__ out)
{
    __shared__ __align__(16) char sWn[64 * 256];    // 16KB pair-major W slice
    __shared__ __align__(16) float sA2[16 * 128];
    __shared__ int sN[16];
    int t = threadIdx.x;
    int nb = gridDim.x;
    for (int l = 4; l >= 0; --l) {
        int cs_row = lvl_start(l + 1);
        int cs_child = lvl_start(l + 2);
        int nt = g_dep_nt[l];
        int items = nt * 4;
        const int* tg = g_dep_tg[l];
        const int* tb = g_dep_tb[l];
        const int* off = g_dep_off[l];
        for (int item = blockIdx.x; item < items; item += nb) {
            __syncthreads();
            int tile = item >> 2, slice = item & 3, c0 = slice * 32;
            int j = tg[tile], b0 = tb[tile];
            int mc = off[j + 1] - b0; if (mc > 16) mc = 16;
            if (t < 16) sN[t] = g_dep_perm[cs_row + b0 + min(t, mc - 1)];
            // W slice staging: pair-major
            const float* Wj = Wsrc + (size_t)j * 16384;
#pragma unroll
            for (int i = 0; i < 2; ++i) {
                int idx = t + 256 * i;        // 0..511
                int kp = idx >> 3, cb = idx & 7;
                float4 r0 = *(const float4*)&Wj[(2 * kp) * 128 + c0 + 4 * cb];
                float4 r1 = *(const float4*)&Wj[(2 * kp + 1) * 128 + c0 + 4 * cb];
                float4 s0 = make_float4(r0.x, r1.x, r0.y, r1.y);
                float4 s1 = make_float4(r0.z, r1.z, r0.w, r1.w);
                unsigned b = (unsigned)(kp * 256 + cb * 32);
                *(float4*)(sWn + sw16(b))      = s0;
                *(float4*)(sWn + sw16(b + 16)) = s1;
            }
            __syncthreads();
            const float4* X4 = (const float4*)g_xz;
            const float4* U4 = (const float4*)g_u;
#pragma unroll
            for (int i = 0; i < 2; ++i) {
                int idx = t + 256 * i; int r = idx >> 5, c = idx & 31;
                int node = sN[r];
                int ch = cs_child + 4 * (node - cs_row);
                float4 v = X4[(size_t)node * 32 + c];
                v = max4(v, U4[(size_t)(ch + 0) * 32 + c]);
                v = max4(v, U4[(size_t)(ch + 1) * 32 + c]);
                v = max4(v, U4[(size_t)(ch + 2) * 32 + c]);
                v = max4(v, U4[(size_t)(ch + 3) * 32 + c]);
                ((float4*)(sA2 + r * 128))[c] = v;
            }
            __syncthreads();
            int r = t >> 4, x16 = t & 15;
            ull accA = 0ull, accB = 0ull;
#pragma unroll 4
            for (int kp = 0; kp < 64; ++kp) {
                ull a = *(const ull*)&sA2[r * 128 + 2 * kp];
                ulonglong2 w = *(const ulonglong2*)(sWn + sw16((unsigned)(kp * 256 + x16 * 16)));
                fma2(accA, a, w.x);
                fma2(accB, a, w.y);
            }
            int node = sN[r];
            int col = c0 + 2 * x16;
            float2 bv = *(const float2*)&bias[j * 128 + col];
            float lo, hi; float2 o;
            unpack2(accA, lo, hi); o.x = fmaxf(lo + hi + bv.x, 0.f);
            unpack2(accB, lo, hi); o.y = fmaxf(lo + hi + bv.y, 0.f);
            *(float2*)&g_u[(size_t)node * 128 + col] = o;
        }
        gridbar(nb);
    }
    // root finalize: out = max(x[0], u of nodes 1..4)
    if (blockIdx.x == 0 && t < 32) {
        const float4* X4 = (const float4*)g_xz;
        const float4* U4 = (const float4*)g_u;
        float4 v = X4[t];
        v = max4(v, U4[1 * 32 + t]);
        v = max4(v, U4[2 * 32 + t]);
        v = max4(v, U4[3 * 32 + t]);
        v = max4(v, U4[4 * 32 + t]);
        ((float4*)out)[t] = v;
    }
}

// ---------------------------------------------------------------------------
extern "C" void kernel_launch(void* const* d_in, const int* in_sizes, int n_in,
                              void* d_out, int out_size) {
    const float* emb     = (const float*)d_in[0];
    const int*   pos_ids = (const int*)d_in[1];
    const int*   dep_ids = (const int*)d_in[2];
    const float* pos_W   = (const float*)d_in[3];
    const float* pos_b   = (const float*)d_in[4];
    const float* dep_W   = (const float*)d_in[5];
    const float* dep_b   = (const float*)d_in[6];

    cudaFuncSetAttribute(gemm_big, cudaFuncAttributeMaxDynamicSharedMemorySize,
                         SMEM_BIG);

    int *d_pos_nt, *d_pos_tg, *d_pos_tb, *d_pos_off, *d_pos_perm;
    int *d_dep_nt, *d_dep_tg, *d_dep_tb, *d_dep_off, *d_dep_perm;
    cudaGetSymbolAddress((void**)&d_pos_nt,   g_pos_nt);
    cudaGetSymbolAddress((void**)&d_pos_tg,   g_pos_tg);
    cudaGetSymbolAddress((void**)&d_pos_tb,   g_pos_tb);
    cudaGetSymbolAddress((void**)&d_pos_off,  g_pos_off);
    cudaGetSymbolAddress((void**)&d_pos_perm, g_pos_perm);
    cudaGetSymbolAddress((void**)&d_dep_nt,   g_dep_nt);
    cudaGetSymbolAddress((void**)&d_dep_tg,   g_dep_tg);
    cudaGetSymbolAddress((void**)&d_dep_tb,   g_dep_tb);
    cudaGetSymbolAddress((void**)&d_dep_off,  g_dep_off);
    cudaGetSymbolAddress((void**)&d_dep_perm, g_dep_perm);
    float* d_xz;
    cudaGetSymbolAddress((void**)&d_xz, g_xz);

    group_kernel<<<8, 1024>>>(pos_ids, dep_ids);

    // pos: all NN nodes -> g_xz
    gemm_big<<<360, 256, SMEM_BIG>>>(0, pos_W, pos_b, emb,
        d_pos_nt, d_pos_tg, d_pos_tb, d_pos_off, d_pos_perm, 0, 0);

    // dep level 6: rows = level-7 nodes (z = x), u -> g_u
    gemm_big<<<302, 256, SMEM_BIG>>>(1, dep_W, dep_b, d_xz,
        d_dep_nt + 6, d_dep_tg + 6 * 320, d_dep_tb + 6 * 320,
        d_dep_off + 6 * (NDEP + 1), d_dep_perm + lvl_start(7),
        lvl_start(7), 0);

    // dep level 5: rows = level-6 nodes, fused max-gather, u -> g_u
    gemm_big<<<110, 256, SMEM_BIG>>>(2, dep_W, dep_b, d_xz,
        d_dep_nt + 5, d_dep_tg + 5 * 320, d_dep_tb + 5 * 320,
        d_dep_off + 5 * (NDEP + 1), d_dep_perm + lvl_start(6),
        lvl_start(6), lvl_start(7));

    // levels 4..0 + root finalize in one persistent kernel
    int dev = 0, nsm = 0, occ = 0;
    cudaGetDevice(&dev);
    cudaDeviceGetAttribute(&nsm, cudaDevAttrMultiProcessorCount, dev);
    cudaOccupancyMaxActiveBlocksPerMultiprocessor(&occ, narrow_all, 256, 0);
    if (occ < 1) occ = 1;
    int grid = nsm * (occ < 2 ? occ : 2);
    narrow_all<<<grid, 256>>>(dep_W, dep_b, (float*)d_out);
}

// round 17
// speedup vs baseline: 1.2020x; 1.0364x over previous
#include <cuda_runtime.h>

#define DD   128
#define NN   21845          // (4^8 - 1) / 3
#define NPOS 18
#define NDEP 46

__host__ __device__ __forceinline__ int lvl_start(int l) {
    return ((1 << (2 * l)) - 1) / 3;
}

typedef unsigned long long ull;

// packed f32x2 helpers (FFMA2: only reachable via PTX fma.rn.f32x2)
__device__ __forceinline__ ull rep2(float s) {
    ull r; asm("mov.b64 %0, {%1, %1};" : "=l"(r) : "f"(s)); return r;
}
__device__ __forceinline__ void fma2(ull& acc, ull a, ull b) {
    asm("fma.rn.f32x2 %0, %1, %2, %0;" : "+l"(acc) : "l"(a), "l"(b));
}
__device__ __forceinline__ void unpack2(ull v, float& lo, float& hi) {
    asm("mov.b64 {%0, %1}, %2;" : "=f"(lo), "=f"(hi) : "l"(v));
}
__device__ __forceinline__ float4 max4(float4 a, float4 b) {
    float4 r;
    r.x = fmaxf(a.x, b.x); r.y = fmaxf(a.y, b.y);
    r.z = fmaxf(a.z, b.z); r.w = fmaxf(a.w, b.w);
    return r;
}

// persistent scratch (device globals: allocation-free)
__device__ float g_xz[NN * DD];            // x from pos stage (read-only after)
__device__ float g_u[NN * DD];             // u outputs keyed by global child idx
__device__ int   g_pos_perm[NN];
__device__ int   g_pos_off[NPOS + 1];
__device__ int   g_pos_tg[384], g_pos_tb[384];
__device__ int   g_pos_nt;
__device__ int   g_dep_perm[NN];
__device__ int   g_dep_off[7][NDEP + 1];
__device__ int   g_dep_tg[7][320], g_dep_tb[7][320];
__device__ int   g_dep_nt[7];
// grid barrier: cnt returns to 0; gen monotonic -> replay-safe
__device__ unsigned g_bar_cnt;
__device__ unsigned g_bar_gen;

__device__ __forceinline__ void gridbar(int nb) {
    __syncthreads();
    if (threadIdx.x == 0) {
        __threadfence();
        unsigned gen = *(volatile unsigned*)&g_bar_gen;
        if (atomicAdd(&g_bar_cnt, 1u) == (unsigned)nb - 1u) {
            atomicExch(&g_bar_cnt, 0u);
            __threadfence();
            atomicAdd(&g_bar_gen, 1u);
        } else {
            while (*(volatile unsigned*)&g_bar_gen == gen) __nanosleep(64);
        }
        __threadfence();
    }
    __syncthreads();
}

// ---------------------------------------------------------------------------
// Grouping: block 0 = pos, blocks 1..7 = dep level b-1
// ---------------------------------------------------------------------------
__global__ void group_kernel(const int* __restrict__ pos_ids,
                             const int* __restrict__ dep_ids) {
    __shared__ int cnt[NDEP];
    __shared__ int off[NDEP + 1];
    int t = threadIdx.x, lane = t & 31;
    const int* ids; int n, ng, base, BM;
    int *perm, *goff, *tg, *tb, *nt_out;
    if (blockIdx.x == 0) {
        ids = pos_ids; n = NN; ng = NPOS; base = 0; BM = 64;
        perm = g_pos_perm; goff = g_pos_off;
        tg = g_pos_tg; tb = g_pos_tb; nt_out = &g_pos_nt;
    } else {
        int l = blockIdx.x - 1;
        base = lvl_start(l + 1); n = 1 << (2 * (l + 1)); ng = NDEP;
        BM = (l >= 5) ? 64 : 16;
        ids = dep_ids + base; perm = g_dep_perm + base; goff = g_dep_off[l];
        tg = g_dep_tg[l]; tb = g_dep_tb[l]; nt_out = &g_dep_nt[l];
    }
    if (t < ng) cnt[t] = 0;
    __syncthreads();
    for (int i0 = 0; i0 < n; i0 += blockDim.x) {
        int i = i0 + t; bool v = (i < n);
        unsigned act = __ballot_sync(0xffffffffu, v);
        if (v) {
            int id = ids[i];
            unsigned m = __match_any_sync(act, id);
            if (lane == __ffs(m) - 1) atomicAdd(&cnt[id], __popc(m));
        }
    }
    __syncthreads();
    if (t == 0) {
        int s = 0;
        for (int j = 0; j < ng; ++j) { off[j] = s; s += cnt[j]; }
        off[ng] = s;
        int nt = 0;
        for (int j = 0; j < ng; ++j) {
            int c = off[j + 1] - off[j];
            for (int k = 0; k < c; k += BM) { tg[nt] = j; tb[nt] = off[j] + k; ++nt; }
        }
        *nt_out = nt;
        for (int j = 0; j <= ng; ++j) goff[j] = off[j];
    }
    __syncthreads();
    if (t < ng) cnt[t] = off[t];   // cursors
    __syncthreads();
    for (int i0 = 0; i0 < n; i0 += blockDim.x) {
        int i = i0 + t; bool v = (i < n);
        unsigned act = __ballot_sync(0xffffffffu, v);
        if (v) {
            int id = ids[i];
            unsigned m = __match_any_sync(act, id);
            int leader = __ffs(m) - 1;
            int prior = __popc(m & ((1u << lane) - 1u));
            int bp = 0;
            if (lane == leader) bp = atomicAdd(&cnt[id], __popc(m));
            bp = __shfl_sync(act, bp, leader);
            perm[bp + prior] = base + i;   // global node index
        }
    }
}

// ---------------------------------------------------------------------------
// Big grouped GEMM (the 123.6us champion core): BM=64 x BN=128, K=128 in smem,
// 256 threads. Thread: 8 rows (ty+8i) x 4 cols as 2 FFMA2 col-pairs with
// rep2-broadcast A. Row-major sW, LDS.128 everywhere.
// mode 0: A = emb[node]                 -> g_xz[node]   (pos)
// mode 1: A = g_xz[node] (leaf z = x)   -> g_u[node]    (dep level 6)
// mode 2: A = max(g_xz[node], u-kids)   -> g_u[node]    (dep level 5)
// ---------------------------------------------------------------------------
#define SMEM_BIG ((16384 + 64 * 128) * 4)

__global__ __launch_bounds__(256, 2)
void gemm_big(int mode, const float* __restrict__ Wsrc,
              const float* __restrict__ bias, const float* __restrict__ srcA,
              const int* __restrict__ nt_p, const int* __restrict__ tg,
              const int* __restrict__ tb, const int* __restrict__ off,
              const int* __restrict__ perm, int cs_row, int cs_child)
{
    int tile = blockIdx.x;
    if (tile >= *nt_p) return;
    extern __shared__ float sm[];
    float* sW = sm;            // 128x128 row-major
    float* sA = sm + 16384;    // 64x128
    __shared__ int sNode[64];
    int t = threadIdx.x;
    int j = tg[tile], b0 = tb[tile];
    int mc = off[j + 1] - b0; if (mc > 64) mc = 64;
    if (t < 64) sNode[t] = perm[b0 + min(t, mc - 1)];
    const float4* W4 = (const float4*)(Wsrc + (size_t)j * 16384);
    float4* sW4 = (float4*)sW;
#pragma unroll
    for (int i = 0; i < 16; ++i) sW4[t + 256 * i] = W4[t + 256 * i];
    __syncthreads();
    if (mode < 2) {
        const float4* A4 = (const float4*)srcA;
#pragma unroll
        for (int i = 0; i < 8; ++i) {
            int idx = t + 256 * i; int r = idx >> 5, c = idx & 31;
            ((float4*)(sA + r * 128))[c] = A4[(size_t)sNode[r] * 32 + c];
        }
    } else {
        // fused max-gather: z[c] = max(x[c], u[4 children])
        const float4* X4 = (const float4*)g_xz;
        const float4* U4 = (const float4*)g_u;
#pragma unroll
        for (int i = 0; i < 8; ++i) {
            int idx = t + 256 * i; int r = idx >> 5, c = idx & 31;
            int node = sNode[r];
            int ch = cs_child + 4 * (node - cs_row);
            float4 v = X4[(size_t)node * 32 + c];
            v = max4(v, U4[(size_t)(ch + 0) * 32 + c]);
            v = max4(v, U4[(size_t)(ch + 1) * 32 + c]);
            v = max4(v, U4[(size_t)(ch + 2) * 32 + c]);
            v = max4(v, U4[(size_t)(ch + 3) * 32 + c]);
            ((float4*)(sA + r * 128))[c] = v;
        }
    }
    __syncthreads();
    int tx = t & 31, ty = t >> 5;
    ull acc2[8][2];
#pragma unroll
    for (int i = 0; i < 8; ++i) { acc2[i][0] = 0ull; acc2[i][1] = 0ull; }
#pragma unroll 4
    for (int k4 = 0; k4 < 32; ++k4) {
        float4 a4[8]; ulonglong2 b2[4];
#pragma unroll
        for (int kk = 0; kk < 4; ++kk)
            b2[kk] = *(const ulonglong2*)&sW[(4 * k4 + kk) * 128 + 4 * tx];
#pragma unroll
        for (int i = 0; i < 8; ++i)
            a4[i] = *(const float4*)&sA[(ty + 8 * i) * 128 + 4 * k4];
#pragma unroll
        for (int i = 0; i < 8; ++i) {
            ull a;
            a = rep2(a4[i].x); fma2(acc2[i][0], a, b2[0].x); fma2(acc2[i][1], a, b2[0].y);
            a = rep2(a4[i].y); fma2(acc2[i][0], a, b2[1].x); fma2(acc2[i][1], a, b2[1].y);
            a = rep2(a4[i].z); fma2(acc2[i][0], a, b2[2].x); fma2(acc2[i][1], a, b2[2].y);
            a = rep2(a4[i].w); fma2(acc2[i][0], a, b2[3].x); fma2(acc2[i][1], a, b2[3].y);
        }
    }
    float4 bv = *(const float4*)&bias[j * 128 + 4 * tx];
    float* dst = (mode == 0) ? g_xz : g_u;
#pragma unroll
    for (int i = 0; i < 8; ++i) {
        int node = sNode[ty + 8 * i];
        float v0, v1, v2, v3;
        unpack2(acc2[i][0], v0, v1);
        unpack2(acc2[i][1], v2, v3);
        float4 o;
        o.x = fmaxf(v0 + bv.x, 0.f);
        o.y = fmaxf(v1 + bv.y, 0.f);
        o.z = fmaxf(v2 + bv.z, 0.f);
        o.w = fmaxf(v3 + bv.w, 0.f);
        *(float4*)&dst[(size_t)node * 128 + 4 * tx] = o;
    }
}

// ---------------------------------------------------------------------------
// Narrow persistent kernel (champion version): dep levels 4..0, fused
// max-gather, STG epilogue, grid barrier between levels, root finalize fold.
// item = (16-row tile) x (32-col slice); 256 thr: 16 rows x 16 thr x 2 cols.
// ---------------------------------------------------------------------------
__global__ __launch_bounds__(256, 2)
void narrow_all(const float* __restrict__ Wsrc, const float* __restrict__ bias,
                float* __restrict__ out)
{
    __shared__ __align__(16) float sWn[128 * 36];
    __shared__ __align__(16) float sA2[16 * 128];
    __shared__ int sN[16];
    int t = threadIdx.x;
    int nb = gridDim.x;
    for (int l = 4; l >= 0; --l) {
        int cs_row = lvl_start(l + 1);      // this level's children (rows)
        int cs_child = lvl_start(l + 2);    // their children (u sources)
        int nt = g_dep_nt[l];
        int items = nt * 4;
        const int* tg = g_dep_tg[l];
        const int* tb = g_dep_tb[l];
        const int* off = g_dep_off[l];
        for (int item = blockIdx.x; item < items; item += nb) {
            __syncthreads();
            int tile = item >> 2, slice = item & 3, c0 = slice * 32;
            int j = tg[tile], b0 = tb[tile];
            int mc = off[j + 1] - b0; if (mc > 16) mc = 16;
            if (t < 16) sN[t] = g_dep_perm[cs_row + b0 + min(t, mc - 1)];
#pragma unroll
            for (int i = 0; i < 4; ++i) {
                int idx = t + 256 * i; int k = idx >> 3, c4 = idx & 7;
                *(float4*)&sWn[k * 36 + 4 * c4] =
                    *(const float4*)&Wsrc[(size_t)j * 16384 + k * 128 + c0 + 4 * c4];
            }
            __syncthreads();
            const float4* X4 = (const float4*)g_xz;
            const float4* U4 = (const float4*)g_u;
#pragma unroll
            for (int i = 0; i < 2; ++i) {
                int idx = t + 256 * i; int r = idx >> 5, c = idx & 31;
                int node = sN[r];
                int ch = cs_child + 4 * (node - cs_row);
                float4 v = X4[(size_t)node * 32 + c];
                v = max4(v, U4[(size_t)(ch + 0) * 32 + c]);
                v = max4(v, U4[(size_t)(ch + 1) * 32 + c]);
                v = max4(v, U4[(size_t)(ch + 2) * 32 + c]);
                v = max4(v, U4[(size_t)(ch + 3) * 32 + c]);
                ((float4*)(sA2 + r * 128))[c] = v;
            }
            __syncthreads();
            int r = t >> 4, x16 = t & 15;
            ull acc = 0ull;
#pragma unroll 4
            for (int k = 0; k < 128; ++k) {
                ull a = rep2(sA2[r * 128 + k]);
                ull w = *(const ull*)&sWn[k * 36 + 2 * x16];
                fma2(acc, a, w);
            }
            int node = sN[r];
            int col = c0 + 2 * x16;
            float2 bv = *(const float2*)&bias[j * 128 + col];
            float a0, a1; unpack2(acc, a0, a1);
            float2 o;
            o.x = fmaxf(a0 + bv.x, 0.f);
            o.y = fmaxf(a1 + bv.y, 0.f);
            *(float2*)&g_u[(size_t)node * 128 + col] = o;
        }
        gridbar(nb);
    }
    // root finalize: out = max(x[0], u of nodes 1..4)
    if (blockIdx.x == 0 && t < 32) {
        const float4* X4 = (const float4*)g_xz;
        const float4* U4 = (const float4*)g_u;
        float4 v = X4[t];
        v = max4(v, U4[1 * 32 + t]);
        v = max4(v, U4[2 * 32 + t]);
        v = max4(v, U4[3 * 32 + t]);
        v = max4(v, U4[4 * 32 + t]);
        ((float4*)out)[t] = v;
    }
}

// ---------------------------------------------------------------------------
extern "C" void kernel_launch(void* const* d_in, const int* in_sizes, int n_in,
                              void* d_out, int out_size) {
    const float* emb     = (const float*)d_in[0];
    const int*   pos_ids = (const int*)d_in[1];
    const int*   dep_ids = (const int*)d_in[2];
    const float* pos_W   = (const float*)d_in[3];
    const float* pos_b   = (const float*)d_in[4];
    const float* dep_W   = (const float*)d_in[5];
    const float* dep_b   = (const float*)d_in[6];

    cudaFuncSetAttribute(gemm_big, cudaFuncAttributeMaxDynamicSharedMemorySize,
                         SMEM_BIG);

    int *d_pos_nt, *d_pos_tg, *d_pos_tb, *d_pos_off, *d_pos_perm;
    int *d_dep_nt, *d_dep_tg, *d_dep_tb, *d_dep_off, *d_dep_perm;
    cudaGetSymbolAddress((void**)&d_pos_nt,   g_pos_nt);
    cudaGetSymbolAddress((void**)&d_pos_tg,   g_pos_tg);
    cudaGetSymbolAddress((void**)&d_pos_tb,   g_pos_tb);
    cudaGetSymbolAddress((void**)&d_pos_off,  g_pos_off);
    cudaGetSymbolAddress((void**)&d_pos_perm, g_pos_perm);
    cudaGetSymbolAddress((void**)&d_dep_nt,   g_dep_nt);
    cudaGetSymbolAddress((void**)&d_dep_tg,   g_dep_tg);
    cudaGetSymbolAddress((void**)&d_dep_tb,   g_dep_tb);
    cudaGetSymbolAddress((void**)&d_dep_off,  g_dep_off);
    cudaGetSymbolAddress((void**)&d_dep_perm, g_dep_perm);
    float* d_xz;
    cudaGetSymbolAddress((void**)&d_xz, g_xz);

    group_kernel<<<8, 1024>>>(pos_ids, dep_ids);

    // pos: all NN nodes -> g_xz
    gemm_big<<<360, 256, SMEM_BIG>>>(0, pos_W, pos_b, emb,
        d_pos_nt, d_pos_tg, d_pos_tb, d_pos_off, d_pos_perm, 0, 0);

    // dep level 6: rows = level-7 nodes (z = x), u -> g_u
    gemm_big<<<302, 256, SMEM_BIG>>>(1, dep_W, dep_b, d_xz,
        d_dep_nt + 6, d_dep_tg + 6 * 320, d_dep_tb + 6 * 320,
        d_dep_off + 6 * (NDEP + 1), d_dep_perm + lvl_start(7),
        lvl_start(7), 0);

    // dep level 5: rows = level-6 nodes, fused max-gather, u -> g_u
    gemm_big<<<110, 256, SMEM_BIG>>>(2, dep_W, dep_b, d_xz,
        d_dep_nt + 5, d_dep_tg + 5 * 320, d_dep_tb + 5 * 320,
        d_dep_off + 5 * (NDEP + 1), d_dep_perm + lvl_start(6),
        lvl_start(6), lvl_start(7));

    // levels 4..0 + root finalize in one persistent kernel
    int dev = 0, nsm = 0, occ = 0;
    cudaGetDevice(&dev);
    cudaDeviceGetAttribute(&nsm, cudaDevAttrMultiProcessorCount, dev);
    cudaOccupancyMaxActiveBlocksPerMultiprocessor(&occ, narrow_all, 256, 0);
    if (occ < 1) occ = 1;
    int grid = nsm * (occ < 2 ? occ : 2);
    narrow_all<<<grid, 256>>>(dep_W, dep_b, (float*)d_out);
}